// round 1
// baseline (speedup 1.0000x reference)
#include <cuda_runtime.h>
#include <math.h>

// Problem constants
#define TT   2048     // B*S tokens
#define Hdim 768
#define Sq   256
#define NBATCH 8
#define NHEAD 12
#define HDm  64
#define FFd  3072
#define NEXP 4

// ---------------- scratch (device globals; no allocation allowed) ----------
__device__ float g_Xa[TT * Hdim];
__device__ float g_Xb[TT * Hdim];
__device__ float g_Hbuf[TT * Hdim];
__device__ float g_Q[TT * Hdim];
__device__ float g_Kb[TT * Hdim];
__device__ float g_Vb[TT * Hdim];
__device__ float g_Sc[NBATCH * NHEAD * Sq * Sq];   // 25 MB scores scratch
__device__ float g_mid[TT * FFd];                  // 25 MB FFN mid
__device__ float g_Fo[TT * Hdim];                  // FFN output (token space)
__device__ float g_mask[TT];                       // additive attention mask
__device__ int   g_idx[TT];                        // note_pos as int (0 = invalid)
__device__ int   g_perm[TT];                       // expert-sorted -> token
__device__ int   g_cnt[NEXP];
__device__ int   g_off[NEXP];

// ---------------- PE add: Xa = x + sinusoidal_pe --------------------------
__global__ void pe_add_kernel(const float* __restrict__ xin, float* __restrict__ out) {
    int t = blockIdx.x;
    int s = t % Sq;
    const float* xr = xin + (size_t)t * Hdim;
    float* yr = out + (size_t)t * Hdim;
    for (int d = threadIdx.x; d < Hdim; d += blockDim.x) {
        int j = d >> 1;
        float div = expf(-(float)(2 * j) * (9.210340371976184f / (float)Hdim));
        float ang = (float)s * div;
        float pe = (d & 1) ? cosf(ang) : sinf(ang);
        yr[d] = xr[d] + pe;
    }
}

// ---------------- note_pos dtype-detect + idx/mask fill --------------------
__global__ void prep_idx_kernel(const void* __restrict__ note_pos_raw) {
    __shared__ int s_or[256];
    __shared__ int s_is64;
    const int* w = (const int*)note_pos_raw;
    int tid = threadIdx.x;
    int acc = 0;
    // OR of odd 32-bit words among the first 2048 words (valid for both dtypes).
    // int64 layout of small nonneg values -> all high words zero; int32 -> nonzero.
    for (int i = tid; i < TT / 2; i += 256) acc |= w[2 * i + 1];
    s_or[tid] = acc; __syncthreads();
    for (int st = 128; st > 0; st >>= 1) {
        if (tid < st) s_or[tid] |= s_or[tid + st];
        __syncthreads();
    }
    if (tid == 0) s_is64 = (s_or[0] == 0);
    __syncthreads();
    bool is64 = (s_is64 != 0);
    for (int t = tid; t < TT; t += 256) {
        long long v = is64 ? ((const long long*)note_pos_raw)[t] : (long long)w[t];
        g_idx[t] = (int)v;
        g_mask[t] = (v != 0) ? 0.0f : -10000.0f;
    }
}

// ---------------- expert routing (single block, shared-mem atomics) --------
__global__ void route_kernel(const int* __restrict__ ntp) {
    __shared__ int sc[NEXP], so[NEXP], scur[NEXP];
    int tid = threadIdx.x;
    if (tid < NEXP) { sc[tid] = 0; scur[tid] = 0; }
    __syncthreads();
    for (int t = tid; t < TT; t += 256) atomicAdd(&sc[ntp[t]], 1);
    __syncthreads();
    if (tid == 0) {
        int o = 0;
        for (int e = 0; e < NEXP; e++) { so[e] = o; o += sc[e]; }
    }
    __syncthreads();
    for (int t = tid; t < TT; t += 256) {
        int e = ntp[t];
        int p = so[e] + atomicAdd(&scur[e], 1);
        g_perm[p] = t;
    }
    __syncthreads();
    if (tid < NEXP) { g_cnt[tid] = sc[tid]; g_off[tid] = so[tid]; }
}

// ---------------- layernorm (block per row, two-pass) ----------------------
__global__ void ln_kernel(const float* __restrict__ X, const float* __restrict__ w,
                          const float* __restrict__ b, float* __restrict__ Y) {
    __shared__ float red[256];
    int t = blockIdx.x, tid = threadIdx.x;
    const float* xr = X + (size_t)t * Hdim;
    float v0 = xr[tid], v1 = xr[tid + 256], v2 = xr[tid + 512];
    red[tid] = v0 + v1 + v2; __syncthreads();
    for (int st = 128; st > 0; st >>= 1) {
        if (tid < st) red[tid] += red[tid + st];
        __syncthreads();
    }
    float mu = red[0] * (1.0f / (float)Hdim);
    __syncthreads();
    float d0 = v0 - mu, d1 = v1 - mu, d2 = v2 - mu;
    red[tid] = d0 * d0 + d1 * d1 + d2 * d2; __syncthreads();
    for (int st = 128; st > 0; st >>= 1) {
        if (tid < st) red[tid] += red[tid + st];
        __syncthreads();
    }
    float var = red[0] * (1.0f / (float)Hdim);
    float rs = rsqrtf(var + 1e-5f);
    float* yr = Y + (size_t)t * Hdim;
    yr[tid]       = d0 * rs * w[tid]       + b[tid];
    yr[tid + 256] = d1 * rs * w[tid + 256] + b[tid + 256];
    yr[tid + 512] = d2 * rs * w[tid + 512] + b[tid + 512];
}

// ---------------- SGEMM: C = act(A @ W + bias) -----------------------------
// 128x128x8 tile, 256 threads, 8x8 per thread.
// MODE 0: plain (M=2048 dense rows)
// MODE 1: FFN1 — A rows gathered via perm (token space), gelu, C in sorted space
// MODE 2: FFN2 — A rows in sorted space, C scattered to token space via perm
template <int MODE>
__global__ __launch_bounds__(256, 2)
void sgemm_kernel(const float* __restrict__ A, const float* __restrict__ W,
                  const float* __restrict__ bias, float* __restrict__ C,
                  int K, int N) {
    int myCnt = TT, myOff = 0;
    const float* Wp = W;
    const float* bp = bias;
    if (MODE != 0) {
        int e = blockIdx.z;
        myCnt = g_cnt[e]; myOff = g_off[e];
        Wp = W + (size_t)e * K * N;
        bp = bias + (size_t)e * N;
        if ((int)blockIdx.x * 128 >= myCnt) return;
    }
    __shared__ float As[8][128];
    __shared__ float Bs[8][128];
    int tid = threadIdx.x;
    int tx = tid & 15, ty = tid >> 4;
    int rowBase = blockIdx.x * 128;
    int colBase = blockIdx.y * 128;

    int lrLoad = rowBase + (tid >> 1);
    int aCol0 = (tid & 1) * 4;
    bool aValid;
    const float* aPtr;
    if (MODE == 0) {
        aValid = true;
        aPtr = A + (size_t)lrLoad * K;
    } else if (MODE == 1) {
        aValid = lrLoad < myCnt;
        aPtr = A + (size_t)(aValid ? g_perm[myOff + lrLoad] : 0) * K;
    } else {
        aValid = lrLoad < myCnt;
        aPtr = A + (size_t)(myOff + (aValid ? lrLoad : 0)) * K;
    }
    int bRow = tid >> 5, bCol = (tid & 31) * 4;

    float acc[8][8] = {};
    for (int k0 = 0; k0 < K; k0 += 8) {
        float4 av = aValid ? *(const float4*)(aPtr + k0 + aCol0)
                           : make_float4(0.f, 0.f, 0.f, 0.f);
        As[aCol0 + 0][tid >> 1] = av.x;
        As[aCol0 + 1][tid >> 1] = av.y;
        As[aCol0 + 2][tid >> 1] = av.z;
        As[aCol0 + 3][tid >> 1] = av.w;
        *(float4*)&Bs[bRow][bCol] =
            *(const float4*)(Wp + (size_t)(k0 + bRow) * N + colBase + bCol);
        __syncthreads();
#pragma unroll
        for (int kk = 0; kk < 8; kk++) {
            float a[8], bv[8];
            *(float4*)(a)     = *(float4*)&As[kk][ty * 8];
            *(float4*)(a + 4) = *(float4*)&As[kk][ty * 8 + 4];
            *(float4*)(bv)     = *(float4*)&Bs[kk][tx * 8];
            *(float4*)(bv + 4) = *(float4*)&Bs[kk][tx * 8 + 4];
#pragma unroll
            for (int i = 0; i < 8; i++)
#pragma unroll
                for (int j = 0; j < 8; j++)
                    acc[i][j] = fmaf(a[i], bv[j], acc[i][j]);
        }
        __syncthreads();
    }
#pragma unroll
    for (int i = 0; i < 8; i++) {
        int lrow = rowBase + ty * 8 + i;
        if (MODE != 0 && lrow >= myCnt) continue;
        int crow;
        if (MODE == 0)      crow = lrow;
        else if (MODE == 1) crow = myOff + lrow;
        else                crow = g_perm[myOff + lrow];
        float* cp = C + (size_t)crow * N + colBase + tx * 8;
#pragma unroll
        for (int j = 0; j < 8; j++) {
            float v = acc[i][j] + bp[colBase + tx * 8 + j];
            if (MODE == 1) v = 0.5f * v * (1.0f + erff(v * 0.70710678118654752f));
            cp[j] = v;
        }
    }
}

// ---------------- attention scores: S[bh] = Q_bh @ K_bh^T + mask -----------
__global__ __launch_bounds__(256)
void scores_kernel() {
    __shared__ float Qs[64][68];
    __shared__ float Ks[64][68];
    int bh = blockIdx.z;
    int b = bh / NHEAD, h = bh % NHEAD;
    int qBase = blockIdx.x * 64, kBase = blockIdx.y * 64;
    const float* Qp = g_Q  + (size_t)(b * Sq + qBase) * Hdim + h * HDm;
    const float* Kp = g_Kb + (size_t)(b * Sq + kBase) * Hdim + h * HDm;
    int tid = threadIdx.x;
    int lr = tid >> 4, lc = (tid & 15) * 4;
#pragma unroll
    for (int p = 0; p < 4; p++) {
        int r = p * 16 + lr;
        *(float4*)&Qs[r][lc] = *(const float4*)(Qp + (size_t)r * Hdim + lc);
        *(float4*)&Ks[r][lc] = *(const float4*)(Kp + (size_t)r * Hdim + lc);
    }
    __syncthreads();
    int tx = tid & 15, ty = tid >> 4;
    float acc[4][4] = {};
#pragma unroll 4
    for (int d = 0; d < 64; d++) {
        float qv[4], kv[4];
#pragma unroll
        for (int i = 0; i < 4; i++) qv[i] = Qs[ty * 4 + i][d];
#pragma unroll
        for (int j = 0; j < 4; j++) kv[j] = Ks[tx * 4 + j][d];
#pragma unroll
        for (int i = 0; i < 4; i++)
#pragma unroll
            for (int j = 0; j < 4; j++)
                acc[i][j] = fmaf(qv[i], kv[j], acc[i][j]);
    }
    float* Sp = g_Sc + (size_t)bh * Sq * Sq;
#pragma unroll
    for (int i = 0; i < 4; i++) {
        int q = qBase + ty * 4 + i;
#pragma unroll
        for (int j = 0; j < 4; j++) {
            int k = kBase + tx * 4 + j;
            Sp[(size_t)q * Sq + k] = acc[i][j] + g_mask[b * Sq + k];
        }
    }
}

// ---------------- softmax over each 256-wide score row (warp per row) ------
__global__ void softmax_kernel() {
    int row = blockIdx.x * 8 + (threadIdx.x >> 5);
    int lane = threadIdx.x & 31;
    float* p = g_Sc + (size_t)row * Sq;
    float v[8];
    float mx = -1e30f;
#pragma unroll
    for (int i = 0; i < 8; i++) { v[i] = p[lane + 32 * i]; mx = fmaxf(mx, v[i]); }
#pragma unroll
    for (int o = 16; o > 0; o >>= 1) mx = fmaxf(mx, __shfl_xor_sync(0xffffffffu, mx, o));
    float sm = 0.f;
#pragma unroll
    for (int i = 0; i < 8; i++) { v[i] = expf(v[i] - mx); sm += v[i]; }
#pragma unroll
    for (int o = 16; o > 0; o >>= 1) sm += __shfl_xor_sync(0xffffffffu, sm, o);
    float inv = 1.0f / sm;
#pragma unroll
    for (int i = 0; i < 8; i++) p[lane + 32 * i] = v[i] * inv;
}

// ---------------- context: X += P @ V (residual fused) ---------------------
__global__ __launch_bounds__(256)
void ctx_kernel(float* __restrict__ X) {
    __shared__ float Ps[64][68];
    __shared__ float Vs[64][68];
    int bh = blockIdx.y;
    int b = bh / NHEAD, h = bh % NHEAD;
    int qBase = blockIdx.x * 64;
    const float* Pp = g_Sc + (size_t)bh * Sq * Sq + (size_t)qBase * Sq;
    int tid = threadIdx.x;
    int lr = tid >> 4, lc = (tid & 15) * 4;
    int tx = tid & 15, ty = tid >> 4;
    float acc[4][4] = {};
    for (int kc = 0; kc < Sq; kc += 64) {
#pragma unroll
        for (int p = 0; p < 4; p++) {
            int r = p * 16 + lr;
            *(float4*)&Ps[r][lc] = *(const float4*)(Pp + (size_t)r * Sq + kc + lc);
            *(float4*)&Vs[r][lc] =
                *(const float4*)(g_Vb + (size_t)(b * Sq + kc + r) * Hdim + h * HDm + lc);
        }
        __syncthreads();
#pragma unroll 4
        for (int kk = 0; kk < 64; kk++) {
            float pv[4], vv[4];
#pragma unroll
            for (int i = 0; i < 4; i++) pv[i] = Ps[ty * 4 + i][kk];
#pragma unroll
            for (int j = 0; j < 4; j++) vv[j] = Vs[kk][tx * 4 + j];
#pragma unroll
            for (int i = 0; i < 4; i++)
#pragma unroll
                for (int j = 0; j < 4; j++)
                    acc[i][j] = fmaf(pv[i], vv[j], acc[i][j]);
        }
        __syncthreads();
    }
#pragma unroll
    for (int i = 0; i < 4; i++) {
        float* xr = X + (size_t)(b * Sq + qBase + ty * 4 + i) * Hdim + h * HDm + tx * 4;
#pragma unroll
        for (int j = 0; j < 4; j++) xr[j] += acc[i][j];
    }
}

// ---------------- scatter: Y[t] = idx? X[idx-1] + F[idx-1] : 0 --------------
__global__ void scatter_kernel(const float* __restrict__ X, float* __restrict__ Y) {
    int t = blockIdx.x;
    int v = g_idx[t];
    float* yr = Y + (size_t)t * Hdim;
    if (v == 0) {
        for (int d = threadIdx.x; d < Hdim; d += blockDim.x) yr[d] = 0.0f;
    } else {
        const float* xr = X   + (size_t)(v - 1) * Hdim;
        const float* fr = g_Fo + (size_t)(v - 1) * Hdim;
        for (int d = threadIdx.x; d < Hdim; d += blockDim.x) yr[d] = xr[d] + fr[d];
    }
}

// ---------------- launch ---------------------------------------------------
extern "C" void kernel_launch(void* const* d_in, const int* in_sizes, int n_in,
                              void* d_out, int out_size) {
    const float* x    = (const float*)d_in[0];
    const void*  np   = d_in[1];
    const int*   ntp  = (const int*)d_in[2];
    const float* Wq   = (const float*)d_in[3];
    const float* bq   = (const float*)d_in[4];
    const float* Wk   = (const float*)d_in[5];
    const float* bk   = (const float*)d_in[6];
    const float* Wv   = (const float*)d_in[7];
    const float* bv   = (const float*)d_in[8];
    const float* ln1w = (const float*)d_in[9];
    const float* ln1b = (const float*)d_in[10];
    const float* ln2w = (const float*)d_in[11];
    const float* ln2b = (const float*)d_in[12];
    const float* W1   = (const float*)d_in[13];
    const float* b1   = (const float*)d_in[14];
    const float* W2   = (const float*)d_in[15];
    const float* b2   = (const float*)d_in[16];
    float* out = (float*)d_out;

    float *Xa, *Xb, *Hb, *Q, *Kb, *Vb, *Mid, *Fo;
    cudaGetSymbolAddress((void**)&Xa, g_Xa);
    cudaGetSymbolAddress((void**)&Xb, g_Xb);
    cudaGetSymbolAddress((void**)&Hb, g_Hbuf);
    cudaGetSymbolAddress((void**)&Q,  g_Q);
    cudaGetSymbolAddress((void**)&Kb, g_Kb);
    cudaGetSymbolAddress((void**)&Vb, g_Vb);
    cudaGetSymbolAddress((void**)&Mid, g_mid);
    cudaGetSymbolAddress((void**)&Fo, g_Fo);

    prep_idx_kernel<<<1, 256>>>(np);
    route_kernel<<<1, 256>>>(ntp);
    pe_add_kernel<<<TT, 256>>>(x, Xa);

    float* Xcur = Xa;
    for (int l = 0; l < 2; l++) {
        float* Xnext = (l == 0) ? Xb : out;
        // --- attention ---
        ln_kernel<<<TT, 256>>>(Xcur, ln1w + l * Hdim, ln1b + l * Hdim, Hb);
        dim3 gqkv(16, 6, 1);
        sgemm_kernel<0><<<gqkv, 256>>>(Hb, Wq + (size_t)l * Hdim * Hdim, bq + l * Hdim, Q,  Hdim, Hdim);
        sgemm_kernel<0><<<gqkv, 256>>>(Hb, Wk + (size_t)l * Hdim * Hdim, bk + l * Hdim, Kb, Hdim, Hdim);
        sgemm_kernel<0><<<gqkv, 256>>>(Hb, Wv + (size_t)l * Hdim * Hdim, bv + l * Hdim, Vb, Hdim, Hdim);
        scores_kernel<<<dim3(4, 4, NBATCH * NHEAD), 256>>>();
        softmax_kernel<<<NBATCH * NHEAD * Sq / 8, 256>>>();
        ctx_kernel<<<dim3(4, NBATCH * NHEAD), 256>>>(Xcur);
        // --- expert FFN ---
        ln_kernel<<<TT, 256>>>(Xcur, ln2w + l * Hdim, ln2b + l * Hdim, Hb);
        sgemm_kernel<1><<<dim3(16, FFd / 128, NEXP), 256>>>(
            Hb, W1 + (size_t)l * NEXP * Hdim * FFd, b1 + (size_t)l * NEXP * FFd, Mid, Hdim, FFd);
        sgemm_kernel<2><<<dim3(16, Hdim / 128, NEXP), 256>>>(
            Mid, W2 + (size_t)l * NEXP * FFd * Hdim, b2 + (size_t)l * NEXP * Hdim, Fo, FFd, Hdim);
        scatter_kernel<<<TT, 256>>>(Xcur, Xnext);
        Xcur = Xnext;
    }
}

// round 5
// speedup vs baseline: 1.9534x; 1.9534x over previous
#include <cuda_runtime.h>
#include <math.h>

#define TT    2048
#define Hdim  768
#define Sq    256
#define NBATCH 8
#define NHEAD 12
#define FFd   3072
#define NEXP  4
#define QKVN  2304
#define NBH   (NBATCH * NHEAD)

// ---------------- scratch (device globals) ---------------------------------
__device__ float g_Xa[TT * Hdim];
__device__ float g_Xb[TT * Hdim];
__device__ float g_Hbuf[TT * Hdim];
__device__ float g_QKV[TT * QKVN];        // packed [Q|K|V] per token
__device__ float g_Wpk[Hdim * QKVN];      // packed QKV weights for current layer
__device__ float g_bpk[QKVN];
__device__ float g_Sc[NBH * Sq * Sq];     // attention scores/probs
__device__ float g_mid[TT * FFd];
__device__ float g_Fo[TT * Hdim];
__device__ float g_mask[TT];
__device__ int   g_idx[TT];
__device__ int   g_perm[TT];
__device__ int   g_cnt[NEXP];
__device__ int   g_off[NEXP];

// ---------------- small helpers --------------------------------------------
__device__ __forceinline__ unsigned f2tf(float f) {
    unsigned u;
    asm("cvt.rna.tf32.f32 %0, %1;" : "=r"(u) : "f"(f));
    return u;
}
__device__ __forceinline__ void mma_tf32(float c[4], const unsigned a[4], const unsigned b[2]) {
    asm volatile(
        "mma.sync.aligned.m16n8k8.row.col.f32.tf32.tf32.f32 "
        "{%0,%1,%2,%3}, {%4,%5,%6,%7}, {%8,%9}, {%0,%1,%2,%3};\n"
        : "+f"(c[0]), "+f"(c[1]), "+f"(c[2]), "+f"(c[3])
        : "r"(a[0]), "r"(a[1]), "r"(a[2]), "r"(a[3]), "r"(b[0]), "r"(b[1]));
}
__device__ __forceinline__ float gelu_f(float v) {
    return 0.5f * v * (1.0f + erff(v * 0.70710678118654752f));
}

// compute 2 k-steps (BK=16) of a 128x128 warp-tiled mma block
__device__ __forceinline__ void mma_compute_128(
    const unsigned (*As)[136], const unsigned (*Bs)[136],
    int warpM, int warpN, int gid, int tig, float acc[4][4][4]) {
#pragma unroll
    for (int ks = 0; ks < 2; ks++) {
        int kb = ks * 8;
        unsigned af[4][4], bf[4][2];
#pragma unroll
        for (int mt = 0; mt < 4; mt++) {
            int m0 = warpM + mt * 16;
            af[mt][0] = As[kb + tig][m0 + gid];
            af[mt][1] = As[kb + tig][m0 + gid + 8];
            af[mt][2] = As[kb + tig + 4][m0 + gid];
            af[mt][3] = As[kb + tig + 4][m0 + gid + 8];
        }
#pragma unroll
        for (int nt = 0; nt < 4; nt++) {
            int n0 = warpN + nt * 8;
            bf[nt][0] = Bs[kb + tig][n0 + gid];
            bf[nt][1] = Bs[kb + tig + 4][n0 + gid];
        }
#pragma unroll
        for (int mt = 0; mt < 4; mt++)
#pragma unroll
            for (int nt = 0; nt < 4; nt++)
                mma_tf32(acc[mt][nt], af[mt], bf[nt]);
    }
}

// ---------------- PE add ----------------------------------------------------
__global__ void pe_add_kernel(const float* __restrict__ xin, float* __restrict__ out) {
    int t = blockIdx.x;
    int s = t % Sq;
    const float* xr = xin + (size_t)t * Hdim;
    float* yr = out + (size_t)t * Hdim;
    for (int d = threadIdx.x; d < Hdim; d += blockDim.x) {
        int j = d >> 1;
        float div = expf(-(float)(2 * j) * (9.210340371976184f / (float)Hdim));
        float ang = (float)s * div;
        float pe = (d & 1) ? cosf(ang) : sinf(ang);
        yr[d] = xr[d] + pe;
    }
}

// ---------------- note_pos dtype-detect + idx/mask fill ---------------------
__global__ void prep_idx_kernel(const void* __restrict__ note_pos_raw) {
    __shared__ int s_or[256];
    __shared__ int s_is64;
    const int* w = (const int*)note_pos_raw;
    int tid = threadIdx.x;
    int acc = 0;
    for (int i = tid; i < TT / 2; i += 256) acc |= w[2 * i + 1];
    s_or[tid] = acc; __syncthreads();
    for (int st = 128; st > 0; st >>= 1) {
        if (tid < st) s_or[tid] |= s_or[tid + st];
        __syncthreads();
    }
    if (tid == 0) s_is64 = (s_or[0] == 0);
    __syncthreads();
    bool is64 = (s_is64 != 0);
    for (int t = tid; t < TT; t += 256) {
        long long v = is64 ? ((const long long*)note_pos_raw)[t] : (long long)w[t];
        g_idx[t] = (int)v;
        g_mask[t] = (v != 0) ? 0.0f : -10000.0f;
    }
}

// ---------------- expert routing -------------------------------------------
__global__ void route_kernel(const int* __restrict__ ntp) {
    __shared__ int sc[NEXP], so[NEXP], scur[NEXP];
    int tid = threadIdx.x;
    if (tid < NEXP) { sc[tid] = 0; scur[tid] = 0; }
    __syncthreads();
    for (int t = tid; t < TT; t += 256) atomicAdd(&sc[ntp[t]], 1);
    __syncthreads();
    if (tid == 0) {
        int o = 0;
        for (int e = 0; e < NEXP; e++) { so[e] = o; o += sc[e]; }
    }
    __syncthreads();
    for (int t = tid; t < TT; t += 256) {
        int e = ntp[t];
        int p = so[e] + atomicAdd(&scur[e], 1);
        g_perm[p] = t;
    }
    __syncthreads();
    if (tid < NEXP) { g_cnt[tid] = sc[tid]; g_off[tid] = so[tid]; }
}

// ---------------- layernorm: warp per row, float4 ---------------------------
__global__ void ln_kernel(const float* __restrict__ X, const float* __restrict__ w,
                          const float* __restrict__ b, float* __restrict__ Y) {
    int row = blockIdx.x * 8 + (threadIdx.x >> 5);
    int lane = threadIdx.x & 31;
    const float4* xr = (const float4*)(X + (size_t)row * Hdim);
    float4 v[6];
    float s = 0.f;
#pragma unroll
    for (int i = 0; i < 6; i++) {
        v[i] = xr[lane + 32 * i];
        s += v[i].x + v[i].y + v[i].z + v[i].w;
    }
#pragma unroll
    for (int o = 16; o > 0; o >>= 1) s += __shfl_xor_sync(0xffffffffu, s, o);
    float mu = s * (1.0f / (float)Hdim);
    float q = 0.f;
#pragma unroll
    for (int i = 0; i < 6; i++) {
        float dx = v[i].x - mu, dy = v[i].y - mu, dz = v[i].z - mu, dw = v[i].w - mu;
        q += dx * dx + dy * dy + dz * dz + dw * dw;
    }
#pragma unroll
    for (int o = 16; o > 0; o >>= 1) q += __shfl_xor_sync(0xffffffffu, q, o);
    float rs = rsqrtf(q * (1.0f / (float)Hdim) + 1e-5f);
    const float4* wp = (const float4*)w;
    const float4* bp = (const float4*)b;
    float4* yr = (float4*)(Y + (size_t)row * Hdim);
#pragma unroll
    for (int i = 0; i < 6; i++) {
        float4 wv = wp[lane + 32 * i], bv = bp[lane + 32 * i];
        float4 o;
        o.x = (v[i].x - mu) * rs * wv.x + bv.x;
        o.y = (v[i].y - mu) * rs * wv.y + bv.y;
        o.z = (v[i].z - mu) * rs * wv.z + bv.z;
        o.w = (v[i].w - mu) * rs * wv.w + bv.w;
        yr[lane + 32 * i] = o;
    }
}

// ---------------- pack QKV weights + bias ----------------------------------
__global__ void pack_qkv_kernel(const float* __restrict__ Wq, const float* __restrict__ Wk,
                                const float* __restrict__ Wv, const float* __restrict__ bq,
                                const float* __restrict__ bk, const float* __restrict__ bv) {
    int k = blockIdx.x;        // 0..767
    int which = blockIdx.y;    // 0..2
    const float* src = (which == 0) ? Wq : (which == 1) ? Wk : Wv;
    float* dst = g_Wpk + (size_t)k * QKVN + which * Hdim;
    for (int n = threadIdx.x; n < Hdim; n += 256)
        dst[n] = src[(size_t)k * Hdim + n];
    if (k == 0) {
        const float* sb = (which == 0) ? bq : (which == 1) ? bk : bv;
        for (int n = threadIdx.x; n < Hdim; n += 256)
            g_bpk[which * Hdim + n] = sb[n];
    }
}

// ---------------- tf32 MMA GEMM: C = act(A @ W + bias) ---------------------
// 128x128x16 tiles, 256 thr (8 warps 2x4), register-staged double buffer.
// MODE 0: dense. MODE 1: gather rows via perm + gelu, C sorted. MODE 2: A sorted, C scattered.
template <int MODE>
__global__ __launch_bounds__(256)
void mma_gemm(const float* __restrict__ A, const float* __restrict__ W,
              const float* __restrict__ bias, float* __restrict__ C,
              int K, int N) {
    int myCnt = TT, myOff = 0;
    const float* Wp = W;
    const float* bp = bias;
    if (MODE != 0) {
        int e = blockIdx.z;
        myCnt = g_cnt[e]; myOff = g_off[e];
        Wp = W + (size_t)e * K * N;
        bp = bias + (size_t)e * N;
        if ((int)blockIdx.x * 128 >= myCnt) return;
    }
    __shared__ unsigned As[16][136];
    __shared__ unsigned Bs[16][136];

    int tid = threadIdx.x;
    int lane = tid & 31, wid = tid >> 5;
    int warpM = (wid >> 2) * 64;
    int warpN = (wid & 3) * 32;
    int gid = lane >> 2, tig = lane & 3;

    int rowBase = blockIdx.x * 128;
    int colBase = blockIdx.y * 128;

    // A loader: thread -> (row = tid>>1, k-half = (tid&1)*8)
    int aRow = tid >> 1;
    int aK = (tid & 1) * 8;
    int lr = rowBase + aRow;
    bool aValid;
    const float* aPtr;
    if (MODE == 0) {
        aValid = true;
        aPtr = A + (size_t)lr * K;
    } else if (MODE == 1) {
        aValid = lr < myCnt;
        aPtr = A + (size_t)(aValid ? g_perm[myOff + lr] : 0) * K;
    } else {
        aValid = lr < myCnt;
        aPtr = A + (size_t)(myOff + (aValid ? lr : 0)) * K;
    }
    // B loader: thread -> (k = tid>>4, n = (tid&15)*8)
    int bK = tid >> 4;
    int bN = (tid & 15) * 8;
    const float* bPtr = Wp + (size_t)bK * N + colBase + bN;

    float acc[4][4][4] = {};
    float4 ra0, ra1, rb0, rb1;
    const float4 z4 = make_float4(0.f, 0.f, 0.f, 0.f);

    // prologue: tile k0=0
    ra0 = aValid ? *(const float4*)(aPtr + aK) : z4;
    ra1 = aValid ? *(const float4*)(aPtr + aK + 4) : z4;
    rb0 = *(const float4*)(bPtr);
    rb1 = *(const float4*)(bPtr + 4);
    {
        As[aK + 0][aRow] = f2tf(ra0.x); As[aK + 1][aRow] = f2tf(ra0.y);
        As[aK + 2][aRow] = f2tf(ra0.z); As[aK + 3][aRow] = f2tf(ra0.w);
        As[aK + 4][aRow] = f2tf(ra1.x); As[aK + 5][aRow] = f2tf(ra1.y);
        As[aK + 6][aRow] = f2tf(ra1.z); As[aK + 7][aRow] = f2tf(ra1.w);
        uint4 u0 = make_uint4(f2tf(rb0.x), f2tf(rb0.y), f2tf(rb0.z), f2tf(rb0.w));
        uint4 u1 = make_uint4(f2tf(rb1.x), f2tf(rb1.y), f2tf(rb1.z), f2tf(rb1.w));
        *(uint4*)&Bs[bK][bN] = u0;
        *(uint4*)&Bs[bK][bN + 4] = u1;
    }
    __syncthreads();

    for (int k0 = 0; k0 < K; k0 += 16) {
        bool hasNext = (k0 + 16) < K;
        if (hasNext) {
            int kk = k0 + 16;
            ra0 = aValid ? *(const float4*)(aPtr + kk + aK) : z4;
            ra1 = aValid ? *(const float4*)(aPtr + kk + aK + 4) : z4;
            rb0 = *(const float4*)(bPtr + (size_t)kk * N);
            rb1 = *(const float4*)(bPtr + (size_t)kk * N + 4);
        }
        mma_compute_128(As, Bs, warpM, warpN, gid, tig, acc);
        __syncthreads();
        if (hasNext) {
            As[aK + 0][aRow] = f2tf(ra0.x); As[aK + 1][aRow] = f2tf(ra0.y);
            As[aK + 2][aRow] = f2tf(ra0.z); As[aK + 3][aRow] = f2tf(ra0.w);
            As[aK + 4][aRow] = f2tf(ra1.x); As[aK + 5][aRow] = f2tf(ra1.y);
            As[aK + 6][aRow] = f2tf(ra1.z); As[aK + 7][aRow] = f2tf(ra1.w);
            uint4 u0 = make_uint4(f2tf(rb0.x), f2tf(rb0.y), f2tf(rb0.z), f2tf(rb0.w));
            uint4 u1 = make_uint4(f2tf(rb1.x), f2tf(rb1.y), f2tf(rb1.z), f2tf(rb1.w));
            *(uint4*)&Bs[bK][bN] = u0;
            *(uint4*)&Bs[bK][bN + 4] = u1;
        }
        __syncthreads();
    }

    // epilogue (NOTE: global tile row = rowBase + local row; guard/index with it)
#pragma unroll
    for (int mt = 0; mt < 4; mt++) {
#pragma unroll
        for (int half = 0; half < 2; half++) {
            int grow = rowBase + warpM + mt * 16 + gid + half * 8;
            if (MODE != 0 && grow >= myCnt) continue;
            int crow;
            if (MODE == 0)      crow = grow;
            else if (MODE == 1) crow = myOff + grow;
            else                crow = g_perm[myOff + grow];
            float* cp = C + (size_t)crow * N;
#pragma unroll
            for (int nt = 0; nt < 4; nt++) {
                int c0 = colBase + warpN + nt * 8 + tig * 2;
                float v0 = acc[mt][nt][half * 2 + 0] + bp[c0];
                float v1 = acc[mt][nt][half * 2 + 1] + bp[c0 + 1];
                if (MODE == 1) { v0 = gelu_f(v0); v1 = gelu_f(v1); }
                float2 vv = make_float2(v0, v1);
                *(float2*)(cp + c0) = vv;
            }
        }
    }
}

// ---------------- attention scores via mma: S = Q K^T + mask ---------------
__global__ __launch_bounds__(256)
void scores_mma_kernel() {
    __shared__ unsigned As[16][136];
    __shared__ unsigned Bs[16][136];
    int bh = blockIdx.z;
    int b = bh / NHEAD, h = bh % NHEAD;
    int qBase = blockIdx.x * 128, kBase = blockIdx.y * 128;
    const float* Qb = g_QKV + (size_t)(b * Sq + qBase) * QKVN + h * 64;
    const float* Kb = g_QKV + (size_t)(b * Sq + kBase) * QKVN + Hdim + h * 64;

    int tid = threadIdx.x;
    int lane = tid & 31, wid = tid >> 5;
    int warpM = (wid >> 2) * 64;
    int warpN = (wid & 3) * 32;
    int gid = lane >> 2, tig = lane & 3;

    int aRow = tid >> 1;
    int aK = (tid & 1) * 8;
    const float* aPtr = Qb + (size_t)aRow * QKVN;
    const float* bPtr = Kb + (size_t)aRow * QKVN;  // transpose-load: aRow = key pos

    float acc[4][4][4] = {};
    for (int k0 = 0; k0 < 64; k0 += 16) {
        float4 ra0 = *(const float4*)(aPtr + k0 + aK);
        float4 ra1 = *(const float4*)(aPtr + k0 + aK + 4);
        float4 rb0 = *(const float4*)(bPtr + k0 + aK);
        float4 rb1 = *(const float4*)(bPtr + k0 + aK + 4);
        As[aK + 0][aRow] = f2tf(ra0.x); As[aK + 1][aRow] = f2tf(ra0.y);
        As[aK + 2][aRow] = f2tf(ra0.z); As[aK + 3][aRow] = f2tf(ra0.w);
        As[aK + 4][aRow] = f2tf(ra1.x); As[aK + 5][aRow] = f2tf(ra1.y);
        As[aK + 6][aRow] = f2tf(ra1.z); As[aK + 7][aRow] = f2tf(ra1.w);
        Bs[aK + 0][aRow] = f2tf(rb0.x); Bs[aK + 1][aRow] = f2tf(rb0.y);
        Bs[aK + 2][aRow] = f2tf(rb0.z); Bs[aK + 3][aRow] = f2tf(rb0.w);
        Bs[aK + 4][aRow] = f2tf(rb1.x); Bs[aK + 5][aRow] = f2tf(rb1.y);
        Bs[aK + 6][aRow] = f2tf(rb1.z); Bs[aK + 7][aRow] = f2tf(rb1.w);
        __syncthreads();
        mma_compute_128(As, Bs, warpM, warpN, gid, tig, acc);
        __syncthreads();
    }
    float* Sp = g_Sc + (size_t)bh * Sq * Sq;
#pragma unroll
    for (int mt = 0; mt < 4; mt++) {
#pragma unroll
        for (int half = 0; half < 2; half++) {
            int q = qBase + warpM + mt * 16 + gid + half * 8;
#pragma unroll
            for (int nt = 0; nt < 4; nt++) {
                int c0 = kBase + warpN + nt * 8 + tig * 2;
                float2 vv;
                vv.x = acc[mt][nt][half * 2 + 0] + g_mask[b * Sq + c0];
                vv.y = acc[mt][nt][half * 2 + 1] + g_mask[b * Sq + c0 + 1];
                *(float2*)(Sp + (size_t)q * Sq + c0) = vv;
            }
        }
    }
}

// ---------------- softmax over each 256-wide row ---------------------------
__global__ void softmax_kernel() {
    int row = blockIdx.x * 8 + (threadIdx.x >> 5);
    int lane = threadIdx.x & 31;
    float* p = g_Sc + (size_t)row * Sq;
    float v[8];
    float mx = -1e30f;
#pragma unroll
    for (int i = 0; i < 8; i++) { v[i] = p[lane + 32 * i]; mx = fmaxf(mx, v[i]); }
#pragma unroll
    for (int o = 16; o > 0; o >>= 1) mx = fmaxf(mx, __shfl_xor_sync(0xffffffffu, mx, o));
    float sm = 0.f;
#pragma unroll
    for (int i = 0; i < 8; i++) { v[i] = expf(v[i] - mx); sm += v[i]; }
#pragma unroll
    for (int o = 16; o > 0; o >>= 1) sm += __shfl_xor_sync(0xffffffffu, sm, o);
    float inv = 1.0f / sm;
#pragma unroll
    for (int i = 0; i < 8; i++) p[lane + 32 * i] = v[i] * inv;
}

// ---------------- ctx via mma: X += P @ V ----------------------------------
// BM=128, BN=64, BK=16, K=256. 8 warps 4x2, warp tile 32x32.
__global__ __launch_bounds__(256)
void ctx_mma_kernel(float* __restrict__ X) {
    __shared__ unsigned As[16][136];
    __shared__ unsigned Bs[16][72];
    int bh = blockIdx.y;
    int b = bh / NHEAD, h = bh % NHEAD;
    int qBase = blockIdx.x * 128;
    const float* Pp = g_Sc + (size_t)bh * Sq * Sq + (size_t)qBase * Sq;
    const float* Vb = g_QKV + 2 * Hdim + h * 64 + (size_t)b * Sq * QKVN;

    int tid = threadIdx.x;
    int lane = tid & 31, wid = tid >> 5;
    int warpM = (wid >> 1) * 32;
    int warpN = (wid & 1) * 32;
    int gid = lane >> 2, tig = lane & 3;

    int aRow = tid >> 1;
    int aK = (tid & 1) * 8;
    const float* aPtr = Pp + (size_t)aRow * Sq;
    int bK = tid >> 4;          // 0..15 (key pos within tile)
    int bN4 = (tid & 15) * 4;   // 0..60

    float acc[2][4][4] = {};
    for (int k0 = 0; k0 < Sq; k0 += 16) {
        float4 ra0 = *(const float4*)(aPtr + k0 + aK);
        float4 ra1 = *(const float4*)(aPtr + k0 + aK + 4);
        float4 rb = *(const float4*)(Vb + (size_t)(k0 + bK) * QKVN + bN4);
        As[aK + 0][aRow] = f2tf(ra0.x); As[aK + 1][aRow] = f2tf(ra0.y);
        As[aK + 2][aRow] = f2tf(ra0.z); As[aK + 3][aRow] = f2tf(ra0.w);
        As[aK + 4][aRow] = f2tf(ra1.x); As[aK + 5][aRow] = f2tf(ra1.y);
        As[aK + 6][aRow] = f2tf(ra1.z); As[aK + 7][aRow] = f2tf(ra1.w);
        uint4 u = make_uint4(f2tf(rb.x), f2tf(rb.y), f2tf(rb.z), f2tf(rb.w));
        *(uint4*)&Bs[bK][bN4] = u;
        __syncthreads();
#pragma unroll
        for (int ks = 0; ks < 2; ks++) {
            int kb = ks * 8;
            unsigned af[2][4], bf[4][2];
#pragma unroll
            for (int mt = 0; mt < 2; mt++) {
                int m0 = warpM + mt * 16;
                af[mt][0] = As[kb + tig][m0 + gid];
                af[mt][1] = As[kb + tig][m0 + gid + 8];
                af[mt][2] = As[kb + tig + 4][m0 + gid];
                af[mt][3] = As[kb + tig + 4][m0 + gid + 8];
            }
#pragma unroll
            for (int nt = 0; nt < 4; nt++) {
                int n0 = warpN + nt * 8;
                bf[nt][0] = Bs[kb + tig][n0 + gid];
                bf[nt][1] = Bs[kb + tig + 4][n0 + gid];
            }
#pragma unroll
            for (int mt = 0; mt < 2; mt++)
#pragma unroll
                for (int nt = 0; nt < 4; nt++)
                    mma_tf32(acc[mt][nt], af[mt], bf[nt]);
        }
        __syncthreads();
    }
    // epilogue: residual add into X
#pragma unroll
    for (int mt = 0; mt < 2; mt++) {
#pragma unroll
        for (int half = 0; half < 2; half++) {
            int q = qBase + warpM + mt * 16 + gid + half * 8;
            float* xr = X + (size_t)(b * Sq + q) * Hdim + h * 64;
#pragma unroll
            for (int nt = 0; nt < 4; nt++) {
                int c0 = warpN + nt * 8 + tig * 2;
                float2 old = *(float2*)(xr + c0);
                old.x += acc[mt][nt][half * 2 + 0];
                old.y += acc[mt][nt][half * 2 + 1];
                *(float2*)(xr + c0) = old;
            }
        }
    }
}

// ---------------- scatter: Y[t] = idx? X[idx-1] + F[idx-1] : 0 --------------
__global__ void scatter_kernel(const float* __restrict__ X, float* __restrict__ Y) {
    int t = blockIdx.x;
    int v = g_idx[t];
    float4* yr = (float4*)(Y + (size_t)t * Hdim);
    int lane = threadIdx.x;
    if (v == 0) {
        if (lane < 192) yr[lane] = make_float4(0.f, 0.f, 0.f, 0.f);
    } else {
        const float4* xr = (const float4*)(X + (size_t)(v - 1) * Hdim);
        const float4* fr = (const float4*)(g_Fo + (size_t)(v - 1) * Hdim);
        if (lane < 192) {
            float4 a = xr[lane], f = fr[lane];
            yr[lane] = make_float4(a.x + f.x, a.y + f.y, a.z + f.z, a.w + f.w);
        }
    }
}

// ---------------- launch ---------------------------------------------------
extern "C" void kernel_launch(void* const* d_in, const int* in_sizes, int n_in,
                              void* d_out, int out_size) {
    const float* x    = (const float*)d_in[0];
    const void*  np   = d_in[1];
    const int*   ntp  = (const int*)d_in[2];
    const float* Wq   = (const float*)d_in[3];
    const float* bq   = (const float*)d_in[4];
    const float* Wk   = (const float*)d_in[5];
    const float* bk   = (const float*)d_in[6];
    const float* Wv   = (const float*)d_in[7];
    const float* bv   = (const float*)d_in[8];
    const float* ln1w = (const float*)d_in[9];
    const float* ln1b = (const float*)d_in[10];
    const float* ln2w = (const float*)d_in[11];
    const float* ln2b = (const float*)d_in[12];
    const float* W1   = (const float*)d_in[13];
    const float* b1   = (const float*)d_in[14];
    const float* W2   = (const float*)d_in[15];
    const float* b2   = (const float*)d_in[16];
    float* out = (float*)d_out;

    float *Xa, *Xb, *Hb, *QKV, *Wpk, *bpk, *Mid, *Fo;
    cudaGetSymbolAddress((void**)&Xa, g_Xa);
    cudaGetSymbolAddress((void**)&Xb, g_Xb);
    cudaGetSymbolAddress((void**)&Hb, g_Hbuf);
    cudaGetSymbolAddress((void**)&QKV, g_QKV);
    cudaGetSymbolAddress((void**)&Wpk, g_Wpk);
    cudaGetSymbolAddress((void**)&bpk, g_bpk);
    cudaGetSymbolAddress((void**)&Mid, g_mid);
    cudaGetSymbolAddress((void**)&Fo, g_Fo);

    prep_idx_kernel<<<1, 256>>>(np);
    route_kernel<<<1, 256>>>(ntp);
    pe_add_kernel<<<TT, 256>>>(x, Xa);

    float* Xcur = Xa;
    for (int l = 0; l < 2; l++) {
        float* Xnext = (l == 0) ? Xb : out;
        size_t lH = (size_t)l * Hdim, lHH = (size_t)l * Hdim * Hdim;
        // --- attention ---
        pack_qkv_kernel<<<dim3(Hdim, 3), 256>>>(Wq + lHH, Wk + lHH, Wv + lHH,
                                                bq + lH, bk + lH, bv + lH);
        ln_kernel<<<TT / 8, 256>>>(Xcur, ln1w + lH, ln1b + lH, Hb);
        mma_gemm<0><<<dim3(16, 18), 256>>>(Hb, Wpk, bpk, QKV, Hdim, QKVN);
        scores_mma_kernel<<<dim3(2, 2, NBH), 256>>>();
        softmax_kernel<<<NBH * Sq / 8, 256>>>();
        ctx_mma_kernel<<<dim3(2, NBH), 256>>>(Xcur);
        // --- expert FFN ---
        ln_kernel<<<TT / 8, 256>>>(Xcur, ln2w + lH, ln2b + lH, Hb);
        mma_gemm<1><<<dim3(16, FFd / 128, NEXP), 256>>>(
            Hb, W1 + (size_t)l * NEXP * Hdim * FFd, b1 + (size_t)l * NEXP * FFd,
            Mid, Hdim, FFd);
        mma_gemm<2><<<dim3(16, Hdim / 128, NEXP), 256>>>(
            Mid, W2 + (size_t)l * NEXP * FFd * Hdim, b2 + (size_t)l * NEXP * Hdim,
            Fo, FFd, Hdim);
        scatter_kernel<<<TT, 256>>>(Xcur, Xnext);
        Xcur = Xnext;
    }
}

// round 8
// speedup vs baseline: 3.9722x; 2.0335x over previous
#include <cuda_runtime.h>
#include <cuda_fp16.h>
#include <math.h>
#include <stdint.h>

#define TT    2048
#define Hdim  768
#define Sq    256
#define NBATCH 8
#define NHEAD 12
#define FFd   3072
#define NEXP  4
#define QKVN  2304
#define NBH   (NBATCH * NHEAD)

// ---------------- scratch (device globals) ---------------------------------
__device__ float  g_Xa[TT * Hdim];
__device__ float  g_Xb[TT * Hdim];
__device__ __half g_Hh[TT * Hdim];          // LN output (fp16)
__device__ float  g_QKV[TT * QKVN];         // packed [Q|K|V] fp32 (attention input)
__device__ float  g_Sc[NBH * Sq * Sq];
__device__ __half g_midh[TT * FFd];         // FFN mid (fp16)
__device__ float  g_Fo[TT * Hdim];
__device__ float  g_mask[TT];
__device__ int    g_idx[TT];
__device__ int    g_perm[TT];
__device__ int    g_cnt[NEXP];
__device__ int    g_off[NEXP];
__device__ __half g_Wqkvh[2 * 3 * Hdim * Hdim];        // [l][q|k|v][768][768]
__device__ __half g_W1h[2 * NEXP * Hdim * FFd];
__device__ __half g_W2h[2 * NEXP * FFd * Hdim];
__device__ float  g_bpk[2 * QKVN];                     // packed qkv bias

// ---------------- helpers ---------------------------------------------------
__device__ __forceinline__ unsigned f2tf(float f) {
    unsigned u;
    asm("cvt.rna.tf32.f32 %0, %1;" : "=r"(u) : "f"(f));
    return u;
}
__device__ __forceinline__ float gelu_f(float v) {
    return 0.5f * v * (1.0f + erff(v * 0.70710678118654752f));
}
__device__ __forceinline__ uint32_t smem_u32(const void* p) {
    uint32_t a;
    asm("{ .reg .u64 t; cvta.to.shared.u64 t, %1; cvt.u32.u64 %0, t; }" : "=r"(a) : "l"(p));
    return a;
}
// swizzles: A rows = 128B, B rows = 256B
#define SWA(o) ((o) ^ (((o) >> 3) & 0x70))
#define SWB(o) ((o) ^ (((o) >> 4) & 0x70))

__device__ __forceinline__ void ldsm4(unsigned r[4], uint32_t addr) {
    asm volatile("ldmatrix.sync.aligned.m8n8.x4.shared.b16 {%0,%1,%2,%3}, [%4];"
                 : "=r"(r[0]), "=r"(r[1]), "=r"(r[2]), "=r"(r[3]) : "r"(addr));
}
__device__ __forceinline__ void ldsm4t(unsigned r[4], uint32_t addr) {
    asm volatile("ldmatrix.sync.aligned.m8n8.x4.trans.shared.b16 {%0,%1,%2,%3}, [%4];"
                 : "=r"(r[0]), "=r"(r[1]), "=r"(r[2]), "=r"(r[3]) : "r"(addr));
}
__device__ __forceinline__ void mma_f16(float c[4], const unsigned a[4],
                                        unsigned b0, unsigned b1) {
    asm volatile(
        "mma.sync.aligned.m16n8k16.row.col.f32.f16.f16.f32 "
        "{%0,%1,%2,%3}, {%4,%5,%6,%7}, {%8,%9}, {%0,%1,%2,%3};\n"
        : "+f"(c[0]), "+f"(c[1]), "+f"(c[2]), "+f"(c[3])
        : "r"(a[0]), "r"(a[1]), "r"(a[2]), "r"(a[3]), "r"(b0), "r"(b1));
}
#define CPASYNC16(dst, src) \
    asm volatile("cp.async.cg.shared.global [%0], [%1], 16;" :: "r"(dst), "l"(src))
#define CPCOMMIT() asm volatile("cp.async.commit_group;" ::: "memory")
#define CPWAIT1() asm volatile("cp.async.wait_group 1;" ::: "memory")
#define CPWAIT0() asm volatile("cp.async.wait_group 0;" ::: "memory")

// ---------------- conversion / pack ----------------------------------------
__global__ void f2h_kernel(const float4* __restrict__ src, uint2* __restrict__ dst, int n4) {
    for (int i = blockIdx.x * blockDim.x + threadIdx.x; i < n4;
         i += gridDim.x * blockDim.x) {
        float4 v = src[i];
        __half2 h0 = __floats2half2_rn(v.x, v.y);
        __half2 h1 = __floats2half2_rn(v.z, v.w);
        uint2 u;
        u.x = *(unsigned*)&h0;
        u.y = *(unsigned*)&h1;
        dst[i] = u;
    }
}
__global__ void pack_bias_kernel(const float* __restrict__ bq, const float* __restrict__ bk,
                                 const float* __restrict__ bv) {
    int i = blockIdx.x * 256 + threadIdx.x;
    if (i < 2 * QKVN) {
        int l = i / QKVN, c = i % QKVN;
        int w = c / Hdim, o = c % Hdim;
        const float* s = (w == 0) ? bq : (w == 1) ? bk : bv;
        g_bpk[i] = s[l * Hdim + o];
    }
}

// ---------------- fp16 mma GEMM: C = act(A @ W + bias) ----------------------
// 128x128 tile, BK=64 fp16, 256 thr (8 warps 2x4, warp tile 64x32), cp.async 2-stage.
// MODE 0: QKV fused (y -> matrix/colblock), fp32 out.
// MODE 1: FFN1, gather A rows via perm, gelu, fp16 out in sorted space.
// MODE 2: FFN2, A sorted fp16, fp32 out scattered to token rows via perm.
extern __shared__ char dynsm[];

template <int MODE>
__global__ __launch_bounds__(256)
void hgemm(const __half* __restrict__ A, const __half* __restrict__ W,
           const float* __restrict__ bias, void* __restrict__ Cv,
           int K, int Nw, int Cstride) {
    int rowBase = blockIdx.x * 128;
    int myCnt = TT, myOff = 0;
    const __half* Wp;
    const float* bp;
    int colW, outCol;
    if (MODE == 0) {
        int y = blockIdx.y, ws = y / 6, yc = y % 6;
        Wp = W + (size_t)ws * Hdim * Hdim;
        colW = yc * 128;
        outCol = y * 128;
        bp = bias + outCol;
    } else {
        int e = blockIdx.z;
        myCnt = g_cnt[e]; myOff = g_off[e];
        if (rowBase >= myCnt) return;
        Wp = W + (size_t)e * K * Nw;
        colW = blockIdx.y * 128;
        outCol = colW;
        bp = bias + (size_t)e * Nw + colW;
    }

    int tid = threadIdx.x;
    int lane = tid & 31, wid = tid >> 5;
    int warpM = (wid >> 2) * 64;   // 2 warp rows
    int warpN = (wid & 3) * 32;    // 4 warp cols
    int gid = lane >> 2, tig = lane & 3;

    uint32_t smA = smem_u32(dynsm);

    // ---- A loader mapping: thread -> row m = tid>>1, 4 x 16B units
    int m = tid >> 1;
    int ukb = (tid & 1) * 4;       // 16B-unit base within 128B row
    bool aValid;
    const __half* ap;
    if (MODE == 0) {
        aValid = true;
        ap = A + (size_t)(rowBase + m) * K;
    } else if (MODE == 1) {
        aValid = (rowBase + m) < myCnt;
        ap = A + (size_t)(aValid ? g_perm[myOff + rowBase + m] : 0) * K;
    } else {
        aValid = (rowBase + m) < myCnt;
        ap = A + (size_t)(myOff + (aValid ? rowBase + m : 0)) * K;
    }
    uint32_t aOff[4];
#pragma unroll
    for (int i = 0; i < 4; i++) aOff[i] = SWA((uint32_t)(m * 128 + (ukb + i) * 16));

    // ---- B loader mapping: thread -> k row = tid>>2, 4 x 16B units
    int bk_ = tid >> 2;
    int unb = (tid & 3) * 4;
    uint32_t bOff[4];
#pragma unroll
    for (int i = 0; i < 4; i++) bOff[i] = SWB((uint32_t)(bk_ * 256 + (unb + i) * 16));

    int nCh = K >> 6;
    float acc[4][4][4] = {};

    // prologue: load chunk 0
    {
        uint32_t ab = smA, bb = smA + 32768;
        const __half* as = ap + ukb * 8;
        const __half* bs = Wp + (size_t)bk_ * Nw + colW + unb * 8;
#pragma unroll
        for (int i = 0; i < 4; i++) CPASYNC16(ab + aOff[i], as + i * 8);
#pragma unroll
        for (int i = 0; i < 4; i++) CPASYNC16(bb + bOff[i], bs + i * 8);
        CPCOMMIT();
    }

    int rA = lane & 15;
    int cA = (lane >> 4) * 8;

    for (int c = 0; c < nCh; c++) {
        if (c + 1 < nCh) {
            int nb = (c + 1) & 1;
            uint32_t ab = smA + nb * 16384, bb = smA + 32768 + nb * 16384;
            const __half* as = ap + (c + 1) * 64 + ukb * 8;
            const __half* bs = Wp + (size_t)((c + 1) * 64 + bk_) * Nw + colW + unb * 8;
#pragma unroll
            for (int i = 0; i < 4; i++) CPASYNC16(ab + aOff[i], as + i * 8);
#pragma unroll
            for (int i = 0; i < 4; i++) CPASYNC16(bb + bOff[i], bs + i * 8);
            CPCOMMIT();
            CPWAIT1();
        } else {
            CPWAIT0();
        }
        __syncthreads();

        uint32_t aB = smA + (c & 1) * 16384;
        uint32_t bB = smA + 32768 + (c & 1) * 16384;
#pragma unroll
        for (int ks = 0; ks < 4; ks++) {
            unsigned afr[4][4], bfr[2][4];
#pragma unroll
            for (int mt = 0; mt < 4; mt++)
                ldsm4(afr[mt], aB + SWA((uint32_t)((warpM + mt * 16 + rA) * 128 +
                                                   (ks * 16 + cA) * 2)));
#pragma unroll
            for (int ng = 0; ng < 2; ng++)
                ldsm4t(bfr[ng], bB + SWB((uint32_t)((ks * 16 + rA) * 256 +
                                                    (warpN + ng * 16 + cA) * 2)));
#pragma unroll
            for (int mt = 0; mt < 4; mt++)
#pragma unroll
                for (int nf = 0; nf < 4; nf++)
                    mma_f16(acc[mt][nf], afr[mt],
                            bfr[nf >> 1][(nf & 1) * 2], bfr[nf >> 1][(nf & 1) * 2 + 1]);
        }
        __syncthreads();
    }

    // ---- epilogue
#pragma unroll
    for (int mt = 0; mt < 4; mt++) {
#pragma unroll
        for (int hf = 0; hf < 2; hf++) {
            int grow = rowBase + warpM + mt * 16 + gid + hf * 8;
            if (MODE != 0 && grow >= myCnt) continue;
#pragma unroll
            for (int nf = 0; nf < 4; nf++) {
                int c0 = warpN + nf * 8 + tig * 2;
                float v0 = acc[mt][nf][hf * 2 + 0] + __ldg(bp + c0);
                float v1 = acc[mt][nf][hf * 2 + 1] + __ldg(bp + c0 + 1);
                if (MODE == 0) {
                    float* C = (float*)Cv;
                    *(float2*)(C + (size_t)grow * Cstride + outCol + c0) =
                        make_float2(v0, v1);
                } else if (MODE == 1) {
                    __half* C = (__half*)Cv;
                    __half2 hv = __floats2half2_rn(gelu_f(v0), gelu_f(v1));
                    *(__half2*)(C + (size_t)(myOff + grow) * Cstride + outCol + c0) = hv;
                } else {
                    float* C = (float*)Cv;
                    int crow = g_perm[myOff + grow];
                    *(float2*)(C + (size_t)crow * Cstride + outCol + c0) =
                        make_float2(v0, v1);
                }
            }
        }
    }
}

// ---------------- legacy tf32 mma helpers (attention) -----------------------
__device__ __forceinline__ void mma_tf32(float c[4], const unsigned a[4], const unsigned b[2]) {
    asm volatile(
        "mma.sync.aligned.m16n8k8.row.col.f32.tf32.tf32.f32 "
        "{%0,%1,%2,%3}, {%4,%5,%6,%7}, {%8,%9}, {%0,%1,%2,%3};\n"
        : "+f"(c[0]), "+f"(c[1]), "+f"(c[2]), "+f"(c[3])
        : "r"(a[0]), "r"(a[1]), "r"(a[2]), "r"(a[3]), "r"(b[0]), "r"(b[1]));
}
__device__ __forceinline__ void mma_compute_128(
    const unsigned (*As)[136], const unsigned (*Bs)[136],
    int warpM, int warpN, int gid, int tig, float acc[4][4][4]) {
#pragma unroll
    for (int ks = 0; ks < 2; ks++) {
        int kb = ks * 8;
        unsigned af[4][4], bf[4][2];
#pragma unroll
        for (int mt = 0; mt < 4; mt++) {
            int m0 = warpM + mt * 16;
            af[mt][0] = As[kb + tig][m0 + gid];
            af[mt][1] = As[kb + tig][m0 + gid + 8];
            af[mt][2] = As[kb + tig + 4][m0 + gid];
            af[mt][3] = As[kb + tig + 4][m0 + gid + 8];
        }
#pragma unroll
        for (int nt = 0; nt < 4; nt++) {
            int n0 = warpN + nt * 8;
            bf[nt][0] = Bs[kb + tig][n0 + gid];
            bf[nt][1] = Bs[kb + tig + 4][n0 + gid];
        }
#pragma unroll
        for (int mt = 0; mt < 4; mt++)
#pragma unroll
            for (int nt = 0; nt < 4; nt++)
                mma_tf32(acc[mt][nt], af[mt], bf[nt]);
    }
}

// ---------------- PE add ----------------------------------------------------
__global__ void pe_add_kernel(const float* __restrict__ xin, float* __restrict__ out) {
    int t = blockIdx.x;
    int s = t % Sq;
    const float* xr = xin + (size_t)t * Hdim;
    float* yr = out + (size_t)t * Hdim;
    for (int d = threadIdx.x; d < Hdim; d += blockDim.x) {
        int j = d >> 1;
        float div = expf(-(float)(2 * j) * (9.210340371976184f / (float)Hdim));
        float ang = (float)s * div;
        float pe = (d & 1) ? cosf(ang) : sinf(ang);
        yr[d] = xr[d] + pe;
    }
}

// ---------------- note_pos dtype-detect + idx/mask fill ---------------------
__global__ void prep_idx_kernel(const void* __restrict__ note_pos_raw) {
    __shared__ int s_or[256];
    __shared__ int s_is64;
    const int* w = (const int*)note_pos_raw;
    int tid = threadIdx.x;
    int acc = 0;
    for (int i = tid; i < TT / 2; i += 256) acc |= w[2 * i + 1];
    s_or[tid] = acc; __syncthreads();
    for (int st = 128; st > 0; st >>= 1) {
        if (tid < st) s_or[tid] |= s_or[tid + st];
        __syncthreads();
    }
    if (tid == 0) s_is64 = (s_or[0] == 0);
    __syncthreads();
    bool is64 = (s_is64 != 0);
    for (int t = tid; t < TT; t += 256) {
        long long v = is64 ? ((const long long*)note_pos_raw)[t] : (long long)w[t];
        g_idx[t] = (int)v;
        g_mask[t] = (v != 0) ? 0.0f : -10000.0f;
    }
}

// ---------------- expert routing -------------------------------------------
__global__ void route_kernel(const int* __restrict__ ntp) {
    __shared__ int sc[NEXP], so[NEXP], scur[NEXP];
    int tid = threadIdx.x;
    if (tid < NEXP) { sc[tid] = 0; scur[tid] = 0; }
    __syncthreads();
    for (int t = tid; t < TT; t += 256) atomicAdd(&sc[ntp[t]], 1);
    __syncthreads();
    if (tid == 0) {
        int o = 0;
        for (int e = 0; e < NEXP; e++) { so[e] = o; o += sc[e]; }
    }
    __syncthreads();
    for (int t = tid; t < TT; t += 256) {
        int e = ntp[t];
        int p = so[e] + atomicAdd(&scur[e], 1);
        g_perm[p] = t;
    }
    __syncthreads();
    if (tid < NEXP) { g_cnt[tid] = sc[tid]; g_off[tid] = so[tid]; }
}

// ---------------- layernorm: warp per row, fp16 out -------------------------
__global__ void ln_kernel(const float* __restrict__ X, const float* __restrict__ w,
                          const float* __restrict__ b, __half* __restrict__ Y) {
    int row = blockIdx.x * 8 + (threadIdx.x >> 5);
    int lane = threadIdx.x & 31;
    const float4* xr = (const float4*)(X + (size_t)row * Hdim);
    float4 v[6];
    float s = 0.f;
#pragma unroll
    for (int i = 0; i < 6; i++) {
        v[i] = xr[lane + 32 * i];
        s += v[i].x + v[i].y + v[i].z + v[i].w;
    }
#pragma unroll
    for (int o = 16; o > 0; o >>= 1) s += __shfl_xor_sync(0xffffffffu, s, o);
    float mu = s * (1.0f / (float)Hdim);
    float q = 0.f;
#pragma unroll
    for (int i = 0; i < 6; i++) {
        float dx = v[i].x - mu, dy = v[i].y - mu, dz = v[i].z - mu, dw = v[i].w - mu;
        q += dx * dx + dy * dy + dz * dz + dw * dw;
    }
#pragma unroll
    for (int o = 16; o > 0; o >>= 1) q += __shfl_xor_sync(0xffffffffu, q, o);
    float rs = rsqrtf(q * (1.0f / (float)Hdim) + 1e-5f);
    const float4* wp = (const float4*)w;
    const float4* bpp = (const float4*)b;
    uint2* yr = (uint2*)(Y + (size_t)row * Hdim);
#pragma unroll
    for (int i = 0; i < 6; i++) {
        float4 wv = wp[lane + 32 * i], bv = bpp[lane + 32 * i];
        __half2 h0 = __floats2half2_rn((v[i].x - mu) * rs * wv.x + bv.x,
                                       (v[i].y - mu) * rs * wv.y + bv.y);
        __half2 h1 = __floats2half2_rn((v[i].z - mu) * rs * wv.z + bv.z,
                                       (v[i].w - mu) * rs * wv.w + bv.w);
        uint2 u;
        u.x = *(unsigned*)&h0;
        u.y = *(unsigned*)&h1;
        yr[lane + 32 * i] = u;
    }
}

// ---------------- attention scores via legacy mma ---------------------------
__global__ __launch_bounds__(256)
void scores_mma_kernel() {
    __shared__ unsigned As[16][136];
    __shared__ unsigned Bs[16][136];
    int bh = blockIdx.z;
    int b = bh / NHEAD, h = bh % NHEAD;
    int qBase = blockIdx.x * 128, kBase = blockIdx.y * 128;
    const float* Qb = g_QKV + (size_t)(b * Sq + qBase) * QKVN + h * 64;
    const float* Kb = g_QKV + (size_t)(b * Sq + kBase) * QKVN + Hdim + h * 64;

    int tid = threadIdx.x;
    int lane = tid & 31, wid = tid >> 5;
    int warpM = (wid >> 2) * 64;
    int warpN = (wid & 3) * 32;
    int gid = lane >> 2, tig = lane & 3;

    int aRow = tid >> 1;
    int aK = (tid & 1) * 8;
    const float* aPtr = Qb + (size_t)aRow * QKVN;
    const float* bPtr = Kb + (size_t)aRow * QKVN;

    float acc[4][4][4] = {};
    for (int k0 = 0; k0 < 64; k0 += 16) {
        float4 ra0 = *(const float4*)(aPtr + k0 + aK);
        float4 ra1 = *(const float4*)(aPtr + k0 + aK + 4);
        float4 rb0 = *(const float4*)(bPtr + k0 + aK);
        float4 rb1 = *(const float4*)(bPtr + k0 + aK + 4);
        As[aK + 0][aRow] = f2tf(ra0.x); As[aK + 1][aRow] = f2tf(ra0.y);
        As[aK + 2][aRow] = f2tf(ra0.z); As[aK + 3][aRow] = f2tf(ra0.w);
        As[aK + 4][aRow] = f2tf(ra1.x); As[aK + 5][aRow] = f2tf(ra1.y);
        As[aK + 6][aRow] = f2tf(ra1.z); As[aK + 7][aRow] = f2tf(ra1.w);
        Bs[aK + 0][aRow] = f2tf(rb0.x); Bs[aK + 1][aRow] = f2tf(rb0.y);
        Bs[aK + 2][aRow] = f2tf(rb0.z); Bs[aK + 3][aRow] = f2tf(rb0.w);
        Bs[aK + 4][aRow] = f2tf(rb1.x); Bs[aK + 5][aRow] = f2tf(rb1.y);
        Bs[aK + 6][aRow] = f2tf(rb1.z); Bs[aK + 7][aRow] = f2tf(rb1.w);
        __syncthreads();
        mma_compute_128(As, Bs, warpM, warpN, gid, tig, acc);
        __syncthreads();
    }
    float* Sp = g_Sc + (size_t)bh * Sq * Sq;
#pragma unroll
    for (int mt = 0; mt < 4; mt++) {
#pragma unroll
        for (int half = 0; half < 2; half++) {
            int q = qBase + warpM + mt * 16 + gid + half * 8;
#pragma unroll
            for (int nt = 0; nt < 4; nt++) {
                int c0 = kBase + warpN + nt * 8 + tig * 2;
                float2 vv;
                vv.x = acc[mt][nt][half * 2 + 0] + g_mask[b * Sq + c0];
                vv.y = acc[mt][nt][half * 2 + 1] + g_mask[b * Sq + c0 + 1];
                *(float2*)(Sp + (size_t)q * Sq + c0) = vv;
            }
        }
    }
}

// ---------------- softmax ----------------------------------------------------
__global__ void softmax_kernel() {
    int row = blockIdx.x * 8 + (threadIdx.x >> 5);
    int lane = threadIdx.x & 31;
    float* p = g_Sc + (size_t)row * Sq;
    float v[8];
    float mx = -1e30f;
#pragma unroll
    for (int i = 0; i < 8; i++) { v[i] = p[lane + 32 * i]; mx = fmaxf(mx, v[i]); }
#pragma unroll
    for (int o = 16; o > 0; o >>= 1) mx = fmaxf(mx, __shfl_xor_sync(0xffffffffu, mx, o));
    float sm = 0.f;
#pragma unroll
    for (int i = 0; i < 8; i++) { v[i] = expf(v[i] - mx); sm += v[i]; }
#pragma unroll
    for (int o = 16; o > 0; o >>= 1) sm += __shfl_xor_sync(0xffffffffu, sm, o);
    float inv = 1.0f / sm;
#pragma unroll
    for (int i = 0; i < 8; i++) p[lane + 32 * i] = v[i] * inv;
}

// ---------------- ctx via legacy mma: X += P @ V ----------------------------
__global__ __launch_bounds__(256)
void ctx_mma_kernel(float* __restrict__ X) {
    __shared__ unsigned As[16][136];
    __shared__ unsigned Bs[16][72];
    int bh = blockIdx.y;
    int b = bh / NHEAD, h = bh % NHEAD;
    int qBase = blockIdx.x * 128;
    const float* Pp = g_Sc + (size_t)bh * Sq * Sq + (size_t)qBase * Sq;
    const float* Vb = g_QKV + 2 * Hdim + h * 64 + (size_t)b * Sq * QKVN;

    int tid = threadIdx.x;
    int lane = tid & 31, wid = tid >> 5;
    int warpM = (wid >> 1) * 32;
    int warpN = (wid & 1) * 32;
    int gid = lane >> 2, tig = lane & 3;

    int aRow = tid >> 1;
    int aK = (tid & 1) * 8;
    const float* aPtr = Pp + (size_t)aRow * Sq;
    int bK = tid >> 4;
    int bN4 = (tid & 15) * 4;

    float acc[2][4][4] = {};
    for (int k0 = 0; k0 < Sq; k0 += 16) {
        float4 ra0 = *(const float4*)(aPtr + k0 + aK);
        float4 ra1 = *(const float4*)(aPtr + k0 + aK + 4);
        float4 rb = *(const float4*)(Vb + (size_t)(k0 + bK) * QKVN + bN4);
        As[aK + 0][aRow] = f2tf(ra0.x); As[aK + 1][aRow] = f2tf(ra0.y);
        As[aK + 2][aRow] = f2tf(ra0.z); As[aK + 3][aRow] = f2tf(ra0.w);
        As[aK + 4][aRow] = f2tf(ra1.x); As[aK + 5][aRow] = f2tf(ra1.y);
        As[aK + 6][aRow] = f2tf(ra1.z); As[aK + 7][aRow] = f2tf(ra1.w);
        uint4 u = make_uint4(f2tf(rb.x), f2tf(rb.y), f2tf(rb.z), f2tf(rb.w));
        *(uint4*)&Bs[bK][bN4] = u;
        __syncthreads();
#pragma unroll
        for (int ks = 0; ks < 2; ks++) {
            int kb = ks * 8;
            unsigned af[2][4], bf[4][2];
#pragma unroll
            for (int mt = 0; mt < 2; mt++) {
                int m0 = warpM + mt * 16;
                af[mt][0] = As[kb + tig][m0 + gid];
                af[mt][1] = As[kb + tig][m0 + gid + 8];
                af[mt][2] = As[kb + tig + 4][m0 + gid];
                af[mt][3] = As[kb + tig + 4][m0 + gid + 8];
            }
#pragma unroll
            for (int nt = 0; nt < 4; nt++) {
                int n0 = warpN + nt * 8;
                bf[nt][0] = Bs[kb + tig][n0 + gid];
                bf[nt][1] = Bs[kb + tig + 4][n0 + gid];
            }
#pragma unroll
            for (int mt = 0; mt < 2; mt++)
#pragma unroll
                for (int nt = 0; nt < 4; nt++)
                    mma_tf32(acc[mt][nt], af[mt], bf[nt]);
        }
        __syncthreads();
    }
#pragma unroll
    for (int mt = 0; mt < 2; mt++) {
#pragma unroll
        for (int half = 0; half < 2; half++) {
            int q = qBase + warpM + mt * 16 + gid + half * 8;
            float* xr = X + (size_t)(b * Sq + q) * Hdim + h * 64;
#pragma unroll
            for (int nt = 0; nt < 4; nt++) {
                int c0 = warpN + nt * 8 + tig * 2;
                float2 old = *(float2*)(xr + c0);
                old.x += acc[mt][nt][half * 2 + 0];
                old.y += acc[mt][nt][half * 2 + 1];
                *(float2*)(xr + c0) = old;
            }
        }
    }
}

// ---------------- scatter ----------------------------------------------------
__global__ void scatter_kernel(const float* __restrict__ X, float* __restrict__ Y) {
    int t = blockIdx.x;
    int v = g_idx[t];
    float4* yr = (float4*)(Y + (size_t)t * Hdim);
    int lane = threadIdx.x;
    if (v == 0) {
        if (lane < 192) yr[lane] = make_float4(0.f, 0.f, 0.f, 0.f);
    } else {
        const float4* xr = (const float4*)(X + (size_t)(v - 1) * Hdim);
        const float4* fr = (const float4*)(g_Fo + (size_t)(v - 1) * Hdim);
        if (lane < 192) {
            float4 a = xr[lane], f = fr[lane];
            yr[lane] = make_float4(a.x + f.x, a.y + f.y, a.z + f.z, a.w + f.w);
        }
    }
}

// ---------------- launch ----------------------------------------------------
#define DYN_SMEM 65536

extern "C" void kernel_launch(void* const* d_in, const int* in_sizes, int n_in,
                              void* d_out, int out_size) {
    const float* x    = (const float*)d_in[0];
    const void*  np   = d_in[1];
    const int*   ntp  = (const int*)d_in[2];
    const float* Wq   = (const float*)d_in[3];
    const float* bq   = (const float*)d_in[4];
    const float* Wk   = (const float*)d_in[5];
    const float* bk   = (const float*)d_in[6];
    const float* Wv   = (const float*)d_in[7];
    const float* bv   = (const float*)d_in[8];
    const float* ln1w = (const float*)d_in[9];
    const float* ln1b = (const float*)d_in[10];
    const float* ln2w = (const float*)d_in[11];
    const float* ln2b = (const float*)d_in[12];
    const float* W1   = (const float*)d_in[13];
    const float* b1   = (const float*)d_in[14];
    const float* W2   = (const float*)d_in[15];
    const float* b2   = (const float*)d_in[16];
    float* out = (float*)d_out;

    float *Xa, *Xb, *QKV, *Fo, *bpk;
    __half *Hh, *Midh, *Wqkvh, *W1h, *W2h;
    cudaGetSymbolAddress((void**)&Xa, g_Xa);
    cudaGetSymbolAddress((void**)&Xb, g_Xb);
    cudaGetSymbolAddress((void**)&Hh, g_Hh);
    cudaGetSymbolAddress((void**)&QKV, g_QKV);
    cudaGetSymbolAddress((void**)&Midh, g_midh);
    cudaGetSymbolAddress((void**)&Fo, g_Fo);
    cudaGetSymbolAddress((void**)&Wqkvh, g_Wqkvh);
    cudaGetSymbolAddress((void**)&W1h, g_W1h);
    cudaGetSymbolAddress((void**)&W2h, g_W2h);
    cudaGetSymbolAddress((void**)&bpk, g_bpk);

    cudaFuncSetAttribute(hgemm<0>, cudaFuncAttributeMaxDynamicSharedMemorySize, DYN_SMEM);
    cudaFuncSetAttribute(hgemm<1>, cudaFuncAttributeMaxDynamicSharedMemorySize, DYN_SMEM);
    cudaFuncSetAttribute(hgemm<2>, cudaFuncAttributeMaxDynamicSharedMemorySize, DYN_SMEM);

    // ---- weight conversions (fp32 -> fp16), once per launch
    const int HH = Hdim * Hdim;
    for (int l = 0; l < 2; l++) {
        f2h_kernel<<<512, 256>>>((const float4*)(Wq + (size_t)l * HH),
                                 (uint2*)(Wqkvh + (size_t)(l * 3 + 0) * HH), HH / 4);
        f2h_kernel<<<512, 256>>>((const float4*)(Wk + (size_t)l * HH),
                                 (uint2*)(Wqkvh + (size_t)(l * 3 + 1) * HH), HH / 4);
        f2h_kernel<<<512, 256>>>((const float4*)(Wv + (size_t)l * HH),
                                 (uint2*)(Wqkvh + (size_t)(l * 3 + 2) * HH), HH / 4);
    }
    f2h_kernel<<<2048, 256>>>((const float4*)W1, (uint2*)W1h, 2 * NEXP * Hdim * FFd / 4);
    f2h_kernel<<<2048, 256>>>((const float4*)W2, (uint2*)W2h, 2 * NEXP * FFd * Hdim / 4);
    pack_bias_kernel<<<(2 * QKVN + 255) / 256, 256>>>(bq, bk, bv);

    prep_idx_kernel<<<1, 256>>>(np);
    route_kernel<<<1, 256>>>(ntp);
    pe_add_kernel<<<TT, 256>>>(x, Xa);

    float* Xcur = Xa;
    for (int l = 0; l < 2; l++) {
        float* Xnext = (l == 0) ? Xb : out;
        size_t lH = (size_t)l * Hdim;
        // --- attention ---
        ln_kernel<<<TT / 8, 256>>>(Xcur, ln1w + lH, ln1b + lH, Hh);
        hgemm<0><<<dim3(16, 18), 256, DYN_SMEM>>>(
            Hh, Wqkvh + (size_t)l * 3 * HH, bpk + l * QKVN, QKV, Hdim, Hdim, QKVN);
        scores_mma_kernel<<<dim3(2, 2, NBH), 256>>>();
        softmax_kernel<<<NBH * Sq / 8, 256>>>();
        ctx_mma_kernel<<<dim3(2, NBH), 256>>>(Xcur);
        // --- expert FFN ---
        ln_kernel<<<TT / 8, 256>>>(Xcur, ln2w + lH, ln2b + lH, Hh);
        hgemm<1><<<dim3(16, FFd / 128, NEXP), 256, DYN_SMEM>>>(
            Hh, W1h + (size_t)l * NEXP * Hdim * FFd, b1 + (size_t)l * NEXP * FFd,
            Midh, Hdim, FFd, FFd);
        hgemm<2><<<dim3(16, Hdim / 128, NEXP), 256, DYN_SMEM>>>(
            Midh, W2h + (size_t)l * NEXP * FFd * Hdim, b2 + (size_t)l * NEXP * Hdim,
            Fo, FFd, Hdim, Hdim);
        scatter_kernel<<<TT, 256>>>(Xcur, Xnext);
        Xcur = Xnext;
    }
}

// round 13
// speedup vs baseline: 6.8135x; 1.7153x over previous
#include <cuda_runtime.h>
#include <cuda_fp16.h>
#include <math.h>
#include <stdint.h>

#define TT    2048
#define Hdim  768
#define Sq    256
#define NBATCH 8
#define NHEAD 12
#define FFd   3072
#define NEXP  4
#define QKVN  2304
#define NBH   (NBATCH * NHEAD)
#define HH    (Hdim * Hdim)

// ---------------- scratch (device globals) ---------------------------------
__device__ float  g_Xa[TT * Hdim];
__device__ float  g_Xb[TT * Hdim];
__device__ __half g_Hh[TT * Hdim];            // LN output (fp16)
__device__ __half g_QKVh[TT * QKVN];          // packed [Q|K|V] fp16
__device__ __half g_midh[TT * FFd];           // FFN mid (fp16)
__device__ float  g_Fo[TT * Hdim];
__device__ float  g_mask[TT];
__device__ int    g_idx[TT];
__device__ int    g_perm[TT];
__device__ int    g_cnt[NEXP];
__device__ int    g_off[NEXP];
__device__ __half g_Wqkvh[2 * 3 * HH];
__device__ __half g_W1h[2 * NEXP * Hdim * FFd];
__device__ __half g_W2h[2 * NEXP * FFd * Hdim];
__device__ float  g_bpk[2 * QKVN];

// ---------------- helpers ---------------------------------------------------
__device__ __forceinline__ float gelu_f(float v) {
    return 0.5f * v * (1.0f + erff(v * 0.70710678118654752f));
}
__device__ __forceinline__ uint32_t smem_u32(const void* p) {
    uint32_t a;
    asm("{ .reg .u64 t; cvta.to.shared.u64 t, %1; cvt.u32.u64 %0, t; }" : "=r"(a) : "l"(p));
    return a;
}
#define SWA(o) ((o) ^ (((o) >> 3) & 0x70))   // 128B rows
#define SWB(o) ((o) ^ (((o) >> 4) & 0x70))   // 256B rows

__device__ __forceinline__ void ldsm4(unsigned r[4], uint32_t addr) {
    asm volatile("ldmatrix.sync.aligned.m8n8.x4.shared.b16 {%0,%1,%2,%3}, [%4];"
                 : "=r"(r[0]), "=r"(r[1]), "=r"(r[2]), "=r"(r[3]) : "r"(addr));
}
__device__ __forceinline__ void ldsm4t(unsigned r[4], uint32_t addr) {
    asm volatile("ldmatrix.sync.aligned.m8n8.x4.trans.shared.b16 {%0,%1,%2,%3}, [%4];"
                 : "=r"(r[0]), "=r"(r[1]), "=r"(r[2]), "=r"(r[3]) : "r"(addr));
}
__device__ __forceinline__ void mma_f16(float c[4], const unsigned a[4],
                                        unsigned b0, unsigned b1) {
    asm volatile(
        "mma.sync.aligned.m16n8k16.row.col.f32.f16.f16.f32 "
        "{%0,%1,%2,%3}, {%4,%5,%6,%7}, {%8,%9}, {%0,%1,%2,%3};\n"
        : "+f"(c[0]), "+f"(c[1]), "+f"(c[2]), "+f"(c[3])
        : "r"(a[0]), "r"(a[1]), "r"(a[2]), "r"(a[3]), "r"(b0), "r"(b1));
}
#define CPASYNC16(dst, src) \
    asm volatile("cp.async.cg.shared.global [%0], [%1], 16;" :: "r"(dst), "l"(src))
#define CPCOMMIT() asm volatile("cp.async.commit_group;" ::: "memory")
#define CPWAIT1() asm volatile("cp.async.wait_group 1;" ::: "memory")
#define CPWAIT0() asm volatile("cp.async.wait_group 0;" ::: "memory")

__device__ __forceinline__ unsigned h2u(__half2 h) { return *(unsigned*)&h; }

// ---------------- weight conversion ----------------------------------------
__global__ void f2h_kernel(const float4* __restrict__ src, uint2* __restrict__ dst, int n4) {
    for (int i = blockIdx.x * blockDim.x + threadIdx.x; i < n4;
         i += gridDim.x * blockDim.x) {
        float4 v = src[i];
        uint2 u;
        u.x = h2u(__floats2half2_rn(v.x, v.y));
        u.y = h2u(__floats2half2_rn(v.z, v.w));
        dst[i] = u;
    }
}
// QKV weights: one launch, grid.y = 6 -> (layer, which)
__global__ void pack_qkv_h(const float4* __restrict__ Wq, const float4* __restrict__ Wk,
                           const float4* __restrict__ Wv) {
    int y = blockIdx.y, l = y / 3, w = y % 3;
    const float4* src = ((w == 0) ? Wq : (w == 1) ? Wk : Wv) + (size_t)l * (HH / 4);
    uint2* dst = (uint2*)(g_Wqkvh + (size_t)y * HH);
    int i = blockIdx.x * 256 + threadIdx.x;
    if (i < HH / 4) {
        float4 v = src[i];
        uint2 u;
        u.x = h2u(__floats2half2_rn(v.x, v.y));
        u.y = h2u(__floats2half2_rn(v.z, v.w));
        dst[i] = u;
    }
}
__global__ void pack_bias_kernel(const float* __restrict__ bq, const float* __restrict__ bk,
                                 const float* __restrict__ bv) {
    int i = blockIdx.x * 256 + threadIdx.x;
    if (i < 2 * QKVN) {
        int l = i / QKVN, c = i % QKVN;
        int w = c / Hdim, o = c % Hdim;
        const float* s = (w == 0) ? bq : (w == 1) ? bk : bv;
        g_bpk[i] = s[l * Hdim + o];
    }
}

// ---------------- fp16 mma GEMM --------------------------------------------
// 128 x BNT tile, BK=64, 256 thr, cp.async 2-stage.
// MODE 0: QKV fused, fp16 out. MODE 1: FFN1 gather+gelu, fp16 out sorted.
// MODE 2: FFN2, fp32 out scattered via perm.
extern __shared__ char dynsm[];

template <int MODE, int BNT>
__global__ __launch_bounds__(256)
void hgemm(const __half* __restrict__ A, const __half* __restrict__ W,
           const float* __restrict__ bias, void* __restrict__ Cv,
           int K, int Nw, int Cstride) {
    constexpr int NF = BNT / 32;       // n8 tiles per warp
    constexpr int NG = BNT / 64;       // ldsm4t groups per ks
    constexpr int BB = 64 * BNT * 2;   // B buffer bytes
    constexpr int UPT = BNT / 32;      // B cp.async per thread

    int rowBase = blockIdx.x * 128;
    int myCnt = TT, myOff = 0;
    const __half* Wp;
    const float* bp;
    int colW, outCol;
    if (MODE == 0) {
        int y = blockIdx.y, ws = y / 6, yc = y % 6;
        Wp = W + (size_t)ws * HH;
        colW = yc * 128;
        outCol = y * 128;
        bp = bias + outCol;
    } else {
        int e = blockIdx.z;
        myCnt = g_cnt[e]; myOff = g_off[e];
        if (rowBase >= myCnt) return;
        Wp = W + (size_t)e * K * Nw;
        colW = blockIdx.y * BNT;
        outCol = colW;
        bp = bias + (size_t)e * Nw + colW;
    }

    int tid = threadIdx.x;
    int lane = tid & 31, wid = tid >> 5;
    int warpM = (wid >> 2) * 64;
    int warpN = (wid & 3) * (BNT / 4);
    int gid = lane >> 2, tig = lane & 3;

    uint32_t smA = smem_u32(dynsm);

    int m = tid >> 1;
    int ukb = (tid & 1) * 4;
    bool aValid;
    const __half* ap;
    if (MODE == 0) {
        aValid = true;
        ap = A + (size_t)(rowBase + m) * K;
    } else if (MODE == 1) {
        aValid = (rowBase + m) < myCnt;
        ap = A + (size_t)(aValid ? g_perm[myOff + rowBase + m] : 0) * K;
    } else {
        aValid = (rowBase + m) < myCnt;
        ap = A + (size_t)(myOff + (aValid ? rowBase + m : 0)) * K;
    }
    uint32_t aOff[4];
#pragma unroll
    for (int i = 0; i < 4; i++) aOff[i] = SWA((uint32_t)(m * 128 + (ukb + i) * 16));

    int bk_ = tid >> 2;
    int unb = (tid & 3) * UPT;
    uint32_t bOff[UPT];
#pragma unroll
    for (int i = 0; i < UPT; i++) {
        uint32_t o = (uint32_t)(bk_ * (BNT * 2) + (unb + i) * 16);
        bOff[i] = (BNT == 128) ? SWB(o) : SWA(o);
    }

    int nCh = K >> 6;
    float acc[4][NF][4] = {};

    {
        uint32_t ab = smA, bb = smA + 32768;
        const __half* as = ap + ukb * 8;
        const __half* bs = Wp + (size_t)bk_ * Nw + colW + unb * 8;
#pragma unroll
        for (int i = 0; i < 4; i++) CPASYNC16(ab + aOff[i], as + i * 8);
#pragma unroll
        for (int i = 0; i < UPT; i++) CPASYNC16(bb + bOff[i], bs + i * 8);
        CPCOMMIT();
    }

    int rA = lane & 15;
    int cA = (lane >> 4) * 8;

    for (int c = 0; c < nCh; c++) {
        if (c + 1 < nCh) {
            int nb = (c + 1) & 1;
            uint32_t ab = smA + nb * 16384, bb = smA + 32768 + nb * BB;
            const __half* as = ap + (c + 1) * 64 + ukb * 8;
            const __half* bs = Wp + (size_t)((c + 1) * 64 + bk_) * Nw + colW + unb * 8;
#pragma unroll
            for (int i = 0; i < 4; i++) CPASYNC16(ab + aOff[i], as + i * 8);
#pragma unroll
            for (int i = 0; i < UPT; i++) CPASYNC16(bb + bOff[i], bs + i * 8);
            CPCOMMIT();
            CPWAIT1();
        } else {
            CPWAIT0();
        }
        __syncthreads();

        uint32_t aB = smA + (c & 1) * 16384;
        uint32_t bB = smA + 32768 + (c & 1) * BB;
#pragma unroll
        for (int ks = 0; ks < 4; ks++) {
            unsigned afr[4][4], bfr[NG][4];
#pragma unroll
            for (int mt = 0; mt < 4; mt++)
                ldsm4(afr[mt], aB + SWA((uint32_t)((warpM + mt * 16 + rA) * 128 +
                                                   (ks * 16 + cA) * 2)));
#pragma unroll
            for (int ng = 0; ng < NG; ng++) {
                uint32_t o = (uint32_t)((ks * 16 + rA) * (BNT * 2) +
                                        (warpN + ng * 16 + cA) * 2);
                ldsm4t(bfr[ng], bB + ((BNT == 128) ? SWB(o) : SWA(o)));
            }
#pragma unroll
            for (int mt = 0; mt < 4; mt++)
#pragma unroll
                for (int nf = 0; nf < NF; nf++)
                    mma_f16(acc[mt][nf], afr[mt],
                            bfr[nf >> 1][(nf & 1) * 2], bfr[nf >> 1][(nf & 1) * 2 + 1]);
        }
        __syncthreads();
    }

#pragma unroll
    for (int mt = 0; mt < 4; mt++) {
#pragma unroll
        for (int hf = 0; hf < 2; hf++) {
            int grow = rowBase + warpM + mt * 16 + gid + hf * 8;
            if (MODE != 0 && grow >= myCnt) continue;
#pragma unroll
            for (int nf = 0; nf < NF; nf++) {
                int c0 = warpN + nf * 8 + tig * 2;
                float v0 = acc[mt][nf][hf * 2 + 0] + __ldg(bp + c0);
                float v1 = acc[mt][nf][hf * 2 + 1] + __ldg(bp + c0 + 1);
                if (MODE == 0) {
                    __half* C = (__half*)Cv;
                    *(__half2*)(C + (size_t)grow * Cstride + outCol + c0) =
                        __floats2half2_rn(v0, v1);
                } else if (MODE == 1) {
                    __half* C = (__half*)Cv;
                    *(__half2*)(C + (size_t)(myOff + grow) * Cstride + outCol + c0) =
                        __floats2half2_rn(gelu_f(v0), gelu_f(v1));
                } else {
                    float* C = (float*)Cv;
                    int crow = g_perm[myOff + grow];
                    *(float2*)(C + (size_t)crow * Cstride + outCol + c0) =
                        make_float2(v0, v1);
                }
            }
        }
    }
}

// ---------------- fused flash attention -------------------------------------
// grid (2, NBH): 128 q rows per block, 8 warps x 16 rows; K/V staged in smem;
// online softmax over 4 key-blocks of 64; X += softmax(QK^T + mask) V.
#define ATTN_SMEM (16384 + 32768 + 32768 + 1024)

__global__ __launch_bounds__(256)
void attn_kernel(float* __restrict__ X) {
    extern __shared__ char sm[];
    uint32_t sQ = smem_u32(sm);
    uint32_t sK = sQ + 16384;
    uint32_t sV = sQ + 49152;
    float* msk = (float*)(sm + 81920);

    int bh = blockIdx.y;
    int b = bh / NHEAD, h = bh % NHEAD;
    int qBase = blockIdx.x * 128;
    const __half* Qg = g_QKVh + (size_t)(b * Sq + qBase) * QKVN + h * 64;
    const __half* Kg = g_QKVh + (size_t)(b * Sq) * QKVN + Hdim + h * 64;
    const __half* Vg = g_QKVh + (size_t)(b * Sq) * QKVN + 2 * Hdim + h * 64;

    int tid = threadIdx.x, lane = tid & 31, wid = tid >> 5;
    int gid = lane >> 2, tig = lane & 3;

    {   // Q: 128 rows, 64B per thread
        int r = tid >> 1, ub = (tid & 1) * 4;
        const __half* src = Qg + (size_t)r * QKVN + ub * 8;
#pragma unroll
        for (int i = 0; i < 4; i++)
            CPASYNC16(sQ + SWA((uint32_t)(r * 128 + (ub + i) * 16)), src + i * 8);
    }
    {   // K, V: 256 rows, 128B per thread each
        const __half* ks = Kg + (size_t)tid * QKVN;
        const __half* vs = Vg + (size_t)tid * QKVN;
#pragma unroll
        for (int i = 0; i < 8; i++) {
            uint32_t o = SWA((uint32_t)(tid * 128 + i * 16));
            CPASYNC16(sK + o, ks + i * 8);
            CPASYNC16(sV + o, vs + i * 8);
        }
    }
    msk[tid] = g_mask[b * Sq + tid];
    CPCOMMIT();
    CPWAIT0();
    __syncthreads();

    int rA = lane & 15, cA = (lane >> 4) * 8;
    unsigned qf[4][4];
#pragma unroll
    for (int ks = 0; ks < 4; ks++)
        ldsm4(qf[ks], sQ + SWA((uint32_t)((wid * 16 + rA) * 128 + (ks * 16 + cA) * 2)));

    float oacc[8][4] = {};
    float m0 = -1e30f, m8 = -1e30f, l0 = 0.f, l8 = 0.f;
    int keyl = (lane & 7) + ((lane >> 4) << 3);
    int dml = ((lane >> 3) & 1) * 8;

    for (int kb = 0; kb < 4; kb++) {
        int keyBase = kb * 64;
        float sacc[8][4] = {};
#pragma unroll
        for (int ks = 0; ks < 4; ks++) {
#pragma unroll
            for (int nf2 = 0; nf2 < 4; nf2++) {
                unsigned kf[4];
                ldsm4(kf, sK + SWA((uint32_t)((keyBase + nf2 * 16 + keyl) * 128 +
                                              (ks * 16 + dml) * 2)));
                mma_f16(sacc[nf2 * 2],     qf[ks], kf[0], kf[1]);
                mma_f16(sacc[nf2 * 2 + 1], qf[ks], kf[2], kf[3]);
            }
        }
        // mask + row max
        float bm0 = -1e30f, bm8 = -1e30f;
#pragma unroll
        for (int nf = 0; nf < 8; nf++) {
            int c0 = keyBase + nf * 8 + tig * 2;
            float mk0 = msk[c0], mk1 = msk[c0 + 1];
            sacc[nf][0] += mk0; sacc[nf][1] += mk1;
            sacc[nf][2] += mk0; sacc[nf][3] += mk1;
            bm0 = fmaxf(bm0, fmaxf(sacc[nf][0], sacc[nf][1]));
            bm8 = fmaxf(bm8, fmaxf(sacc[nf][2], sacc[nf][3]));
        }
#pragma unroll
        for (int o = 1; o < 4; o <<= 1) {
            bm0 = fmaxf(bm0, __shfl_xor_sync(0xffffffffu, bm0, o));
            bm8 = fmaxf(bm8, __shfl_xor_sync(0xffffffffu, bm8, o));
        }
        float nm0 = fmaxf(m0, bm0), nm8 = fmaxf(m8, bm8);
        float sc0 = __expf(m0 - nm0), sc8 = __expf(m8 - nm8);
        m0 = nm0; m8 = nm8;
        float ls0 = 0.f, ls8 = 0.f;
        unsigned pa[4][4];
#pragma unroll
        for (int nf = 0; nf < 8; nf++) {
            float p0 = __expf(sacc[nf][0] - m0), p1 = __expf(sacc[nf][1] - m0);
            float p2 = __expf(sacc[nf][2] - m8), p3 = __expf(sacc[nf][3] - m8);
            ls0 += p0 + p1; ls8 += p2 + p3;
            unsigned h01 = h2u(__floats2half2_rn(p0, p1));
            unsigned h23 = h2u(__floats2half2_rn(p2, p3));
            int j = nf >> 1;
            if ((nf & 1) == 0) { pa[j][0] = h01; pa[j][1] = h23; }
            else               { pa[j][2] = h01; pa[j][3] = h23; }
        }
#pragma unroll
        for (int o = 1; o < 4; o <<= 1) {
            ls0 += __shfl_xor_sync(0xffffffffu, ls0, o);
            ls8 += __shfl_xor_sync(0xffffffffu, ls8, o);
        }
        l0 = l0 * sc0 + ls0;
        l8 = l8 * sc8 + ls8;
#pragma unroll
        for (int nd = 0; nd < 8; nd++) {
            oacc[nd][0] *= sc0; oacc[nd][1] *= sc0;
            oacc[nd][2] *= sc8; oacc[nd][3] *= sc8;
        }
        // P @ V
#pragma unroll
        for (int j = 0; j < 4; j++) {
#pragma unroll
            for (int nd2 = 0; nd2 < 4; nd2++) {
                unsigned vf[4];
                ldsm4t(vf, sV + SWA((uint32_t)((keyBase + j * 16 + rA) * 128 +
                                               (nd2 * 16 + cA) * 2)));
                mma_f16(oacc[nd2 * 2],     pa[j], vf[0], vf[1]);
                mma_f16(oacc[nd2 * 2 + 1], pa[j], vf[2], vf[3]);
            }
        }
    }
    // epilogue: X += O / l
    float inv0 = 1.f / l0, inv8 = 1.f / l8;
    int q0 = b * Sq + qBase + wid * 16 + gid;
#pragma unroll
    for (int nd = 0; nd < 8; nd++) {
        int col = h * 64 + nd * 8 + tig * 2;
        float* x0 = X + (size_t)q0 * Hdim + col;
        float* x8 = X + (size_t)(q0 + 8) * Hdim + col;
        float2 v0 = *(float2*)x0, v8 = *(float2*)x8;
        v0.x += oacc[nd][0] * inv0; v0.y += oacc[nd][1] * inv0;
        v8.x += oacc[nd][2] * inv8; v8.y += oacc[nd][3] * inv8;
        *(float2*)x0 = v0; *(float2*)x8 = v8;
    }
}

// ---------------- PE add ----------------------------------------------------
__global__ void pe_add_kernel(const float* __restrict__ xin, float* __restrict__ out) {
    int t = blockIdx.x;
    int s = t % Sq;
    const float* xr = xin + (size_t)t * Hdim;
    float* yr = out + (size_t)t * Hdim;
    for (int d = threadIdx.x; d < Hdim; d += blockDim.x) {
        int j = d >> 1;
        float div = expf(-(float)(2 * j) * (9.210340371976184f / (float)Hdim));
        float ang = (float)s * div;
        float pe = (d & 1) ? cosf(ang) : sinf(ang);
        yr[d] = xr[d] + pe;
    }
}

// ---------------- note_pos dtype-detect + idx/mask fill ---------------------
__global__ void prep_idx_kernel(const void* __restrict__ note_pos_raw) {
    __shared__ int s_or[256];
    __shared__ int s_is64;
    const int* w = (const int*)note_pos_raw;
    int tid = threadIdx.x;
    int acc = 0;
    for (int i = tid; i < TT / 2; i += 256) acc |= w[2 * i + 1];
    s_or[tid] = acc; __syncthreads();
    for (int st = 128; st > 0; st >>= 1) {
        if (tid < st) s_or[tid] |= s_or[tid + st];
        __syncthreads();
    }
    if (tid == 0) s_is64 = (s_or[0] == 0);
    __syncthreads();
    bool is64 = (s_is64 != 0);
    for (int t = tid; t < TT; t += 256) {
        long long v = is64 ? ((const long long*)note_pos_raw)[t] : (long long)w[t];
        g_idx[t] = (int)v;
        g_mask[t] = (v != 0) ? 0.0f : -10000.0f;
    }
}

// ---------------- expert routing -------------------------------------------
__global__ void route_kernel(const int* __restrict__ ntp) {
    __shared__ int sc[NEXP], so[NEXP], scur[NEXP];
    int tid = threadIdx.x;
    if (tid < NEXP) { sc[tid] = 0; scur[tid] = 0; }
    __syncthreads();
    for (int t = tid; t < TT; t += 256) atomicAdd(&sc[ntp[t]], 1);
    __syncthreads();
    if (tid == 0) {
        int o = 0;
        for (int e = 0; e < NEXP; e++) { so[e] = o; o += sc[e]; }
    }
    __syncthreads();
    for (int t = tid; t < TT; t += 256) {
        int e = ntp[t];
        int p = so[e] + atomicAdd(&scur[e], 1);
        g_perm[p] = t;
    }
    __syncthreads();
    if (tid < NEXP) { g_cnt[tid] = sc[tid]; g_off[tid] = so[tid]; }
}

// ---------------- layernorm: warp per row, fp16 out -------------------------
__global__ void ln_kernel(const float* __restrict__ X, const float* __restrict__ w,
                          const float* __restrict__ b, __half* __restrict__ Y) {
    int row = blockIdx.x * 8 + (threadIdx.x >> 5);
    int lane = threadIdx.x & 31;
    const float4* xr = (const float4*)(X + (size_t)row * Hdim);
    float4 v[6];
    float s = 0.f;
#pragma unroll
    for (int i = 0; i < 6; i++) {
        v[i] = xr[lane + 32 * i];
        s += v[i].x + v[i].y + v[i].z + v[i].w;
    }
#pragma unroll
    for (int o = 16; o > 0; o >>= 1) s += __shfl_xor_sync(0xffffffffu, s, o);
    float mu = s * (1.0f / (float)Hdim);
    float q = 0.f;
#pragma unroll
    for (int i = 0; i < 6; i++) {
        float dx = v[i].x - mu, dy = v[i].y - mu, dz = v[i].z - mu, dw = v[i].w - mu;
        q += dx * dx + dy * dy + dz * dz + dw * dw;
    }
#pragma unroll
    for (int o = 16; o > 0; o >>= 1) q += __shfl_xor_sync(0xffffffffu, q, o);
    float rs = rsqrtf(q * (1.0f / (float)Hdim) + 1e-5f);
    const float4* wp = (const float4*)w;
    const float4* bpp = (const float4*)b;
    uint2* yr = (uint2*)(Y + (size_t)row * Hdim);
#pragma unroll
    for (int i = 0; i < 6; i++) {
        float4 wv = wp[lane + 32 * i], bv = bpp[lane + 32 * i];
        uint2 u;
        u.x = h2u(__floats2half2_rn((v[i].x - mu) * rs * wv.x + bv.x,
                                    (v[i].y - mu) * rs * wv.y + bv.y));
        u.y = h2u(__floats2half2_rn((v[i].z - mu) * rs * wv.z + bv.z,
                                    (v[i].w - mu) * rs * wv.w + bv.w));
        yr[lane + 32 * i] = u;
    }
}

// ---------------- scatter ----------------------------------------------------
__global__ void scatter_kernel(const float* __restrict__ X, float* __restrict__ Y) {
    int t = blockIdx.x;
    int v = g_idx[t];
    float4* yr = (float4*)(Y + (size_t)t * Hdim);
    int lane = threadIdx.x;
    if (v == 0) {
        if (lane < 192) yr[lane] = make_float4(0.f, 0.f, 0.f, 0.f);
    } else {
        const float4* xr = (const float4*)(X + (size_t)(v - 1) * Hdim);
        const float4* fr = (const float4*)(g_Fo + (size_t)(v - 1) * Hdim);
        if (lane < 192) {
            float4 a = xr[lane], f = fr[lane];
            yr[lane] = make_float4(a.x + f.x, a.y + f.y, a.z + f.z, a.w + f.w);
        }
    }
}

// ---------------- launch ----------------------------------------------------
extern "C" void kernel_launch(void* const* d_in, const int* in_sizes, int n_in,
                              void* d_out, int out_size) {
    const float* x    = (const float*)d_in[0];
    const void*  np   = d_in[1];
    const int*   ntp  = (const int*)d_in[2];
    const float* Wq   = (const float*)d_in[3];
    const float* bq   = (const float*)d_in[4];
    const float* Wk   = (const float*)d_in[5];
    const float* bk   = (const float*)d_in[6];
    const float* Wv   = (const float*)d_in[7];
    const float* bv   = (const float*)d_in[8];
    const float* ln1w = (const float*)d_in[9];
    const float* ln1b = (const float*)d_in[10];
    const float* ln2w = (const float*)d_in[11];
    const float* ln2b = (const float*)d_in[12];
    const float* W1   = (const float*)d_in[13];
    const float* b1   = (const float*)d_in[14];
    const float* W2   = (const float*)d_in[15];
    const float* b2   = (const float*)d_in[16];
    float* out = (float*)d_out;

    float *Xa, *Xb, *Fo, *bpk;
    __half *Hh, *QKVh, *Midh, *Wqkvh, *W1h, *W2h;
    cudaGetSymbolAddress((void**)&Xa, g_Xa);
    cudaGetSymbolAddress((void**)&Xb, g_Xb);
    cudaGetSymbolAddress((void**)&Hh, g_Hh);
    cudaGetSymbolAddress((void**)&QKVh, g_QKVh);
    cudaGetSymbolAddress((void**)&Midh, g_midh);
    cudaGetSymbolAddress((void**)&Fo, g_Fo);
    cudaGetSymbolAddress((void**)&Wqkvh, g_Wqkvh);
    cudaGetSymbolAddress((void**)&W1h, g_W1h);
    cudaGetSymbolAddress((void**)&W2h, g_W2h);
    cudaGetSymbolAddress((void**)&bpk, g_bpk);

    cudaFuncSetAttribute(hgemm<0, 128>, cudaFuncAttributeMaxDynamicSharedMemorySize, 65536);
    cudaFuncSetAttribute(hgemm<1, 128>, cudaFuncAttributeMaxDynamicSharedMemorySize, 65536);
    cudaFuncSetAttribute(hgemm<2, 64>,  cudaFuncAttributeMaxDynamicSharedMemorySize, 49152);
    cudaFuncSetAttribute(attn_kernel,   cudaFuncAttributeMaxDynamicSharedMemorySize, ATTN_SMEM);

    // weight conversions (every call; deterministic)
    pack_qkv_h<<<dim3((HH / 4 + 255) / 256, 6), 256>>>(
        (const float4*)Wq, (const float4*)Wk, (const float4*)Wv);
    f2h_kernel<<<2048, 256>>>((const float4*)W1, (uint2*)W1h, 2 * NEXP * Hdim * FFd / 4);
    f2h_kernel<<<2048, 256>>>((const float4*)W2, (uint2*)W2h, 2 * NEXP * FFd * Hdim / 4);
    pack_bias_kernel<<<(2 * QKVN + 255) / 256, 256>>>(bq, bk, bv);

    prep_idx_kernel<<<1, 256>>>(np);
    route_kernel<<<1, 256>>>(ntp);
    pe_add_kernel<<<TT, 256>>>(x, Xa);

    float* Xcur = Xa;
    for (int l = 0; l < 2; l++) {
        float* Xnext = (l == 0) ? Xb : out;
        size_t lH = (size_t)l * Hdim;
        // --- attention ---
        ln_kernel<<<TT / 8, 256>>>(Xcur, ln1w + lH, ln1b + lH, Hh);
        hgemm<0, 128><<<dim3(16, 18), 256, 65536>>>(
            Hh, Wqkvh + (size_t)l * 3 * HH, bpk + l * QKVN, QKVh, Hdim, Hdim, QKVN);
        attn_kernel<<<dim3(2, NBH), 256, ATTN_SMEM>>>(Xcur);
        // --- expert FFN ---
        ln_kernel<<<TT / 8, 256>>>(Xcur, ln2w + lH, ln2b + lH, Hh);
        hgemm<1, 128><<<dim3(16, FFd / 128, NEXP), 256, 65536>>>(
            Hh, W1h + (size_t)l * NEXP * Hdim * FFd, b1 + (size_t)l * NEXP * FFd,
            Midh, Hdim, FFd, FFd);
        hgemm<2, 64><<<dim3(16, Hdim / 64, NEXP), 256, 49152>>>(
            Midh, W2h + (size_t)l * NEXP * FFd * Hdim, b2 + (size_t)l * NEXP * Hdim,
            Fo, FFd, Hdim, Hdim);
        scatter_kernel<<<TT, 256>>>(Xcur, Xnext);
        Xcur = Xnext;
    }
}